// round 2
// baseline (speedup 1.0000x reference)
#include <cuda_runtime.h>
#include <math.h>
#include <stdint.h>

#define Hdim 1024
#define H3   3072
#define Gdim 256
#define Ldim 128
#define NMAX 16384

// ---------------- scratch (device globals; no allocations) ----------------
__device__ float g_msg[NMAX * Hdim];
__device__ float g_xg[2][(size_t)NMAX * H3];
__device__ float g_h[2][2][Gdim * Hdim];
__device__ int   g_start[Gdim + 1];

// ---------------- helpers ----------------
__device__ __forceinline__ uint32_t f2tf(float f) {
    uint32_t u;
    asm("cvt.rna.tf32.f32 %0, %1;" : "=r"(u) : "f"(f));
    return u;
}

__device__ __forceinline__ void mma8(float* d, const uint32_t* a, const uint32_t* b) {
    asm volatile(
        "mma.sync.aligned.m16n8k8.row.col.f32.tf32.tf32.f32 "
        "{%0,%1,%2,%3}, {%4,%5,%6,%7}, {%8,%9}, {%0,%1,%2,%3};\n"
        : "+f"(d[0]), "+f"(d[1]), "+f"(d[2]), "+f"(d[3])
        : "r"(a[0]), "r"(a[1]), "r"(a[2]), "r"(a[3]), "r"(b[0]), "r"(b[1]));
}

// ---------------- meta: segment starts ----------------
__global__ void k_meta(const int* __restrict__ batch, int n) {
    int g = threadIdx.x;
    if (g > Gdim) return;
    int lo = 0, hi = n;
    while (lo < hi) {
        int mid = (lo + hi) >> 1;
        if (batch[mid] < g) lo = mid + 1; else hi = mid;
    }
    g_start[g] = lo;
}

// ---------------- message = relu(h_atom + bias) ----------------
__global__ void k_message(const float* __restrict__ h_atom,
                          const float* __restrict__ bias, int n4) {
    int i = blockIdx.x * blockDim.x + threadIdx.x;
    if (i >= n4) return;
    float4 v = ((const float4*)h_atom)[i];
    float4 b = ((const float4*)bias)[i & (Hdim / 4 - 1)];
    v.x = fmaxf(v.x + b.x, 0.f);
    v.y = fmaxf(v.y + b.y, 0.f);
    v.z = fmaxf(v.z + b.z, 0.f);
    v.w = fmaxf(v.w + b.w, 0.f);
    ((float4*)g_msg)[i] = v;
}

// ---------------- h0 = segment max ----------------
__global__ void k_h0(const float* __restrict__ h_atom) {
    int g = blockIdx.x;
    int c = threadIdx.x * 4;
    int s0 = g_start[g], s1 = g_start[g + 1];
    float4 m = make_float4(-3.4e38f, -3.4e38f, -3.4e38f, -3.4e38f);
    for (int r = s0; r < s1; r++) {
        float4 v = *(const float4*)&h_atom[(size_t)r * Hdim + c];
        m.x = fmaxf(m.x, v.x); m.y = fmaxf(m.y, v.y);
        m.z = fmaxf(m.z, v.z); m.w = fmaxf(m.w, v.w);
    }
    if (s1 == s0) m = make_float4(0.f, 0.f, 0.f, 0.f);
    *(float4*)&g_h[0][0][g * Hdim + c] = m;
    *(float4*)&g_h[1][0][g * Hdim + c] = m;
}

// =====================================================================
// Input GEMM (3xTF32 tensor): XG[n x 3072] = msg @ W_ih^T + b_ih
// Block tile 128(M) x 64(N), K-chunk 32, 256 threads.
// Warps: wm = wid>>1 (0..3) -> 32 rows; wn = wid&1 (0..1) -> 32 cols.
// Smem in MMA-fragment order: sA [buf][cp][kf4][mfr8][lane32][4],
//                             sB [buf][cp][kf4][nfr8][lane32][2].
// =====================================================================
__global__ void __launch_bounds__(256) k_gemm_t(
    const float* __restrict__ w_f, const float* __restrict__ bi_f,
    const float* __restrict__ w_b, const float* __restrict__ bi_b, int n)
{
    extern __shared__ uint32_t sm[];
    uint32_t* sA = sm;            // 16384 uints
    uint32_t* sB = sm + 16384;    // 8192 uints
    const int SA_CP = 4096;       // hi->lo copy stride (uints)
    const int SB_CP = 2048;

    int dir = blockIdx.z;
    const float* W  = dir ? w_b : w_f;
    const float* Bv = dir ? bi_b : bi_f;
    float* XG = g_xg[dir];
    int n0 = blockIdx.x * 64;
    int m0 = blockIdx.y * 128;

    int tid = threadIdx.x, lane = tid & 31, wid = tid >> 5;
    int wm = wid >> 1, wn = wid & 1;

    // loader: row = p*32 + lr, cols lc..lc+3
    int lr = tid >> 3, lc = (tid & 7) * 4;
    int kf_l = lc >> 3;
    int ccq  = (lc >> 2) & 1;

    float acc[2][4][4];
#pragma unroll
    for (int m = 0; m < 2; m++)
#pragma unroll
        for (int nf = 0; nf < 4; nf++)
#pragma unroll
            for (int e = 0; e < 4; e++) acc[m][nf][e] = 0.f;

    float pa[4][4], pb[2][4];

    auto loadA = [&](int k0) {
#pragma unroll
        for (int p = 0; p < 4; p++) {
            int r = m0 + p * 32 + lr;
            float4 v = (r < n) ? *(const float4*)&g_msg[(size_t)r * Hdim + k0 + lc]
                               : make_float4(0, 0, 0, 0);
            pa[p][0] = v.x; pa[p][1] = v.y; pa[p][2] = v.z; pa[p][3] = v.w;
        }
    };
    auto loadB = [&](int k0) {
#pragma unroll
        for (int p = 0; p < 2; p++) {
            float4 v = *(const float4*)&W[(size_t)(n0 + p * 32 + lr) * Hdim + k0 + lc];
            pb[p][0] = v.x; pb[p][1] = v.y; pb[p][2] = v.z; pb[p][3] = v.w;
        }
    };
    auto storeAB = [&](int buf) {
#pragma unroll
        for (int p = 0; p < 4; p++) {
            int row = p * 32 + lr;
            int mfr = row >> 4, rr = row & 15;
#pragma unroll
            for (int e = 0; e < 4; e++) {
                int lane_t = ((rr & 7) << 2) | e;
                int slot = (ccq << 1) | (rr >> 3);
                int idx = ((((buf * 2) * 4 + kf_l) * 8 + mfr) * 32 + lane_t) * 4 + slot;
                float x = pa[p][e];
                uint32_t hb = f2tf(x);
                sA[idx] = hb;
                sA[idx + SA_CP] = f2tf(x - __uint_as_float(hb));
            }
        }
#pragma unroll
        for (int p = 0; p < 2; p++) {
            int rt = p * 32 + lr;
            int nfr = rt >> 3, jj8 = rt & 7;
#pragma unroll
            for (int e = 0; e < 4; e++) {
                int lane_t = (jj8 << 2) | e;
                int idx = ((((buf * 2) * 4 + kf_l) * 8 + nfr) * 32 + lane_t) * 2 + ccq;
                float x = pb[p][e];
                uint32_t hb = f2tf(x);
                sB[idx] = hb;
                sB[idx + SB_CP] = f2tf(x - __uint_as_float(hb));
            }
        }
    };
    auto compute = [&](int buf) {
#pragma unroll
        for (int kf = 0; kf < 4; kf++) {
            uint32_t ah[2][4], al[2][4];
#pragma unroll
            for (int m = 0; m < 2; m++) {
                int mfr = wm * 2 + m;
                int base = ((((buf * 2) * 4 + kf) * 8 + mfr) * 32 + lane) * 4;
                *(uint4*)ah[m] = *(const uint4*)&sA[base];
                *(uint4*)al[m] = *(const uint4*)&sA[base + SA_CP];
            }
            uint32_t bh[4][2], bl[4][2];
#pragma unroll
            for (int nf = 0; nf < 4; nf++) {
                int nfr = wn * 4 + nf;
                int base = ((((buf * 2) * 4 + kf) * 8 + nfr) * 32 + lane) * 2;
                *(uint2*)bh[nf] = *(const uint2*)&sB[base];
                *(uint2*)bl[nf] = *(const uint2*)&sB[base + SB_CP];
            }
#pragma unroll
            for (int m = 0; m < 2; m++)
#pragma unroll
                for (int nf = 0; nf < 4; nf++) {
                    mma8(acc[m][nf], ah[m], bh[nf]);
                    mma8(acc[m][nf], al[m], bh[nf]);
                    mma8(acc[m][nf], ah[m], bl[nf]);
                }
        }
    };

    loadA(0); loadB(0);
    storeAB(0);
    __syncthreads();
    for (int kc = 0; kc < 32; kc++) {
        int buf = kc & 1;
        if (kc + 1 < 32) { loadA((kc + 1) * 32); loadB((kc + 1) * 32); }
        compute(buf);
        if (kc + 1 < 32) { storeAB(buf ^ 1); __syncthreads(); }
    }

    // epilogue: add bias, store
    float2 bvv[4];
#pragma unroll
    for (int nf = 0; nf < 4; nf++) {
        int col = n0 + wn * 32 + nf * 8 + (lane & 3) * 2;
        bvv[nf] = *(const float2*)&Bv[col];
    }
#pragma unroll
    for (int m = 0; m < 2; m++)
#pragma unroll
        for (int half = 0; half < 2; half++) {
            int row = m0 + wm * 32 + m * 16 + (lane >> 2) + half * 8;
            if (row < n) {
#pragma unroll
                for (int nf = 0; nf < 4; nf++) {
                    int col = n0 + wn * 32 + nf * 8 + (lane & 3) * 2;
                    float2 o;
                    o.x = acc[m][nf][half * 2 + 0] + bvv[nf].x;
                    o.y = acc[m][nf][half * 2 + 1] + bvv[nf].y;
                    *(float2*)&XG[(size_t)row * H3 + col] = o;
                }
            }
        }
}

// =====================================================================
// GRU step (3xTF32 tensor): gates = h @ W_hh^T, fused gate epilogue.
// Block tile 64(g) x 32(jj) x 3 gates, K-chunk 32, 256 threads.
// Warps: wm = wid>>2 (0..1) -> 32 g; wn = wid&3 -> 8 jj (per gate).
// sA [buf][cp][kf4][mfr4][lane32][4] = 8192 uints
// sB [buf][cp][kf4][nfr12][lane32][2] = 12288 uints  (nfr = gate*4 + jfr)
// =====================================================================
__global__ void __launch_bounds__(256) k_step_t(
    const float* __restrict__ whh_f, const float* __restrict__ bhh_f,
    const float* __restrict__ bih_f,
    const float* __restrict__ whh_b, const float* __restrict__ bhh_b,
    const float* __restrict__ bih_b,
    float* __restrict__ out, int s)
{
    extern __shared__ uint32_t sm[];
    uint32_t* sA = sm;           // 8192 uints
    uint32_t* sB = sm + 8192;    // 12288 uints
    const int SA_CP = 2048;
    const int SB_CP = 3072;

    int dir = blockIdx.z;
    const float* W  = dir ? whh_b : whh_f;
    const float* Bh = dir ? bhh_b : bhh_f;
    const float* Bi = dir ? bih_b : bih_f;
    const float* xg = g_xg[dir];
    const float* hin  = g_h[dir][s & 1];
    float*       hout = g_h[dir][(s & 1) ^ 1];
    int t = dir ? (Ldim - 1 - s) : s;

    int j0 = blockIdx.x * 32;
    int g0 = blockIdx.y * 64;

    int tid = threadIdx.x, lane = tid & 31, wid = tid >> 5;
    int wm = wid >> 2, wn = wid & 3;
    int lr = tid >> 3, lc = (tid & 7) * 4;
    int kf_l = lc >> 3;
    int ccq  = (lc >> 2) & 1;

    float acc[2][3][4];
#pragma unroll
    for (int m = 0; m < 2; m++)
#pragma unroll
        for (int gt = 0; gt < 3; gt++)
#pragma unroll
            for (int e = 0; e < 4; e++) acc[m][gt][e] = 0.f;

    float pa[2][4], pb[3][4];

    auto loadA = [&](int k0) {
#pragma unroll
        for (int p = 0; p < 2; p++) {
            float4 v = *(const float4*)&hin[(g0 + p * 32 + lr) * Hdim + k0 + lc];
            pa[p][0] = v.x; pa[p][1] = v.y; pa[p][2] = v.z; pa[p][3] = v.w;
        }
    };
    auto loadB = [&](int k0) {
#pragma unroll
        for (int p = 0; p < 3; p++) {
            int rt = p * 32 + lr;
            int gt = rt >> 5, jl = rt & 31;
            float4 v = *(const float4*)&W[(size_t)(gt * Hdim + j0 + jl) * Hdim + k0 + lc];
            pb[p][0] = v.x; pb[p][1] = v.y; pb[p][2] = v.z; pb[p][3] = v.w;
        }
    };
    auto storeAB = [&](int buf) {
#pragma unroll
        for (int p = 0; p < 2; p++) {
            int row = p * 32 + lr;
            int mfr = row >> 4, rr = row & 15;
#pragma unroll
            for (int e = 0; e < 4; e++) {
                int lane_t = ((rr & 7) << 2) | e;
                int slot = (ccq << 1) | (rr >> 3);
                int idx = ((((buf * 2) * 4 + kf_l) * 4 + mfr) * 32 + lane_t) * 4 + slot;
                float x = pa[p][e];
                uint32_t hb = f2tf(x);
                sA[idx] = hb;
                sA[idx + SA_CP] = f2tf(x - __uint_as_float(hb));
            }
        }
#pragma unroll
        for (int p = 0; p < 3; p++) {
            int rt = p * 32 + lr;
            int gt = rt >> 5, jl = rt & 31;
            int nfr = gt * 4 + (jl >> 3), jj8 = jl & 7;
#pragma unroll
            for (int e = 0; e < 4; e++) {
                int lane_t = (jj8 << 2) | e;
                int idx = ((((buf * 2) * 4 + kf_l) * 12 + nfr) * 32 + lane_t) * 2 + ccq;
                float x = pb[p][e];
                uint32_t hb = f2tf(x);
                sB[idx] = hb;
                sB[idx + SB_CP] = f2tf(x - __uint_as_float(hb));
            }
        }
    };
    auto compute = [&](int buf) {
#pragma unroll
        for (int kf = 0; kf < 4; kf++) {
            uint32_t ah[2][4], al[2][4];
#pragma unroll
            for (int m = 0; m < 2; m++) {
                int mfr = wm * 2 + m;
                int base = ((((buf * 2) * 4 + kf) * 4 + mfr) * 32 + lane) * 4;
                *(uint4*)ah[m] = *(const uint4*)&sA[base];
                *(uint4*)al[m] = *(const uint4*)&sA[base + SA_CP];
            }
            uint32_t bh[3][2], bl[3][2];
#pragma unroll
            for (int gt = 0; gt < 3; gt++) {
                int nfr = gt * 4 + wn;
                int base = ((((buf * 2) * 4 + kf) * 12 + nfr) * 32 + lane) * 2;
                *(uint2*)bh[gt] = *(const uint2*)&sB[base];
                *(uint2*)bl[gt] = *(const uint2*)&sB[base + SB_CP];
            }
#pragma unroll
            for (int m = 0; m < 2; m++)
#pragma unroll
                for (int gt = 0; gt < 3; gt++) {
                    mma8(acc[m][gt], ah[m], bh[gt]);
                    mma8(acc[m][gt], al[m], bh[gt]);
                    mma8(acc[m][gt], ah[m], bl[gt]);
                }
        }
    };

    loadA(0); loadB(0);
    storeAB(0);
    __syncthreads();
    for (int kc = 0; kc < 32; kc++) {
        int buf = kc & 1;
        if (kc + 1 < 32) { loadA((kc + 1) * 32); loadB((kc + 1) * 32); }
        compute(buf);
        if (kc + 1 < 32) { storeAB(buf ^ 1); __syncthreads(); }
    }

    // ---- fused gate epilogue + scatter ----
#pragma unroll
    for (int m = 0; m < 2; m++) {
#pragma unroll
        for (int half = 0; half < 2; half++) {
            int g = g0 + wm * 32 + m * 16 + (lane >> 2) + half * 8;
            int st = g_start[g];
            int cnt = g_start[g + 1] - st;
            bool valid = (t < cnt);
            size_t abase = (size_t)(st + t) * H3;
#pragma unroll
            for (int cp = 0; cp < 2; cp++) {
                int j = j0 + wn * 8 + (lane & 3) * 2 + cp;
                int ai = half * 2 + cp;
                float xr, xz, xn;
                if (valid) {
                    xr = xg[abase + j];
                    xz = xg[abase + Hdim + j];
                    xn = xg[abase + 2 * Hdim + j];
                } else {
                    xr = Bi[j]; xz = Bi[Hdim + j]; xn = Bi[2 * Hdim + j];
                }
                float r  = 1.f / (1.f + expf(-(xr + acc[m][0][ai] + Bh[j])));
                float z  = 1.f / (1.f + expf(-(xz + acc[m][1][ai] + Bh[Hdim + j])));
                float nn = tanhf(xn + r * (acc[m][2][ai] + Bh[2 * Hdim + j]));
                float hprev = hin[g * Hdim + j];
                float hnew = (1.f - z) * nn + z * hprev;
                hout[g * Hdim + j] = hnew;
                if (valid)
                    out[(size_t)(st + t) * (2 * Hdim) + dir * Hdim + j] = hnew;
            }
        }
    }
}

// ---------------- host launcher ----------------
extern "C" void kernel_launch(void* const* d_in, const int* in_sizes, int n_in,
                              void* d_out, int out_size)
{
    int nAtoms = in_sizes[0] / Hdim;

    const float* h_atom = (const float*)d_in[0];
    int iBatch, iBias, iWihF, iWhhF, iBihF, iBhhF, iWihB, iWhhB, iBihB, iBhhB;
    if (in_sizes[1] == nAtoms) {
        iBatch = 1; iBias = 2; iWihF = 3; iWhhF = 4; iBihF = 5; iBhhF = 6;
        iWihB = 7; iWhhB = 8; iBihB = 9; iBhhB = 10;
    } else {
        iBias = 1; iWihF = 2; iWhhF = 3; iBihF = 4; iBhhF = 5;
        iWihB = 6; iWhhB = 7; iBihB = 8; iBhhB = 9; iBatch = 10;
    }

    const int*   batch = (const int*)d_in[iBatch];
    const float* bias  = (const float*)d_in[iBias];
    const float* wihf  = (const float*)d_in[iWihF];
    const float* whhf  = (const float*)d_in[iWhhF];
    const float* bihf  = (const float*)d_in[iBihF];
    const float* bhhf  = (const float*)d_in[iBhhF];
    const float* wihb  = (const float*)d_in[iWihB];
    const float* whhb  = (const float*)d_in[iWhhB];
    const float* bihb  = (const float*)d_in[iBihB];
    const float* bhhb  = (const float*)d_in[iBhhB];
    float* out = (float*)d_out;

    const int SMEM_G = (16384 + 8192) * 4;   // 98304 B
    const int SMEM_S = (8192 + 12288) * 4;   // 81920 B
    cudaFuncSetAttribute(k_gemm_t, cudaFuncAttributeMaxDynamicSharedMemorySize, SMEM_G);
    cudaFuncSetAttribute(k_step_t, cudaFuncAttributeMaxDynamicSharedMemorySize, SMEM_S);

    k_meta<<<1, 512>>>(batch, nAtoms);

    int n4 = nAtoms * Hdim / 4;
    k_message<<<(n4 + 255) / 256, 256>>>(h_atom, bias, n4);

    k_h0<<<Gdim, 256>>>(h_atom);

    dim3 gg(H3 / 64, (nAtoms + 127) / 128, 2);
    k_gemm_t<<<gg, 256, SMEM_G>>>(wihf, bihf, wihb, bihb, nAtoms);

    dim3 gs(Hdim / 32, Gdim / 64, 2);
    for (int s = 0; s < Ldim; s++) {
        k_step_t<<<gs, 256, SMEM_S>>>(whhf, bhhf, bihf, whhb, bhhb, bihb, out, s);
    }
}

// round 3
// speedup vs baseline: 1.7871x; 1.7871x over previous
#include <cuda_runtime.h>
#include <cuda_bf16.h>
#include <math.h>
#include <stdint.h>

#define Hdim 1024
#define H3   3072
#define Gdim 256
#define Ldim 128
#define NMAX 16384
#define WELEM (H3 * Hdim)

// ---------------- scratch (device globals; no allocations) ----------------
__device__ uint32_t g_msg_hi[NMAX * Hdim / 2];
__device__ uint32_t g_msg_lo[NMAX * Hdim / 2];
__device__ uint32_t g_w_hi[4][WELEM / 2];     // 0=w_ih_f 1=w_hh_f 2=w_ih_b 3=w_hh_b
__device__ uint32_t g_w_lo[4][WELEM / 2];
__device__ float    g_xg[2][(size_t)NMAX * H3];
__device__ float    g_h[2][2][Gdim * Hdim];
__device__ uint32_t g_h_hi[2][2][Gdim * Hdim / 2];
__device__ uint32_t g_h_lo[2][2][Gdim * Hdim / 2];
__device__ int      g_start[Gdim + 1];

// ---------------- helpers ----------------
__device__ __forceinline__ void split2(float x, float y, uint32_t& hi, uint32_t& lo) {
    __nv_bfloat16 hx = __float2bfloat16_rn(x), hy = __float2bfloat16_rn(y);
    __nv_bfloat16 lx = __float2bfloat16_rn(x - __bfloat162float(hx));
    __nv_bfloat16 ly = __float2bfloat16_rn(y - __bfloat162float(hy));
    __nv_bfloat162 h; h.x = hx; h.y = hy;
    __nv_bfloat162 l; l.x = lx; l.y = ly;
    hi = *reinterpret_cast<uint32_t*>(&h);
    lo = *reinterpret_cast<uint32_t*>(&l);
}

__device__ __forceinline__ void mma16(float* d, const uint32_t* a, const uint32_t* b) {
    asm volatile(
        "mma.sync.aligned.m16n8k16.row.col.f32.bf16.bf16.f32 "
        "{%0,%1,%2,%3}, {%4,%5,%6,%7}, {%8,%9}, {%0,%1,%2,%3};\n"
        : "+f"(d[0]), "+f"(d[1]), "+f"(d[2]), "+f"(d[3])
        : "r"(a[0]), "r"(a[1]), "r"(a[2]), "r"(a[3]), "r"(b[0]), "r"(b[1]));
}

// ---------------- meta: segment starts ----------------
__global__ void k_meta(const int* __restrict__ batch, int n) {
    int g = threadIdx.x;
    if (g > Gdim) return;
    int lo = 0, hi = n;
    while (lo < hi) {
        int mid = (lo + hi) >> 1;
        if (batch[mid] < g) lo = mid + 1; else hi = mid;
    }
    g_start[g] = lo;
}

// ---------------- weight pre-split (fp32 -> bf16 hi/lo) ----------------
__global__ void k_split_w(const float* __restrict__ w0, const float* __restrict__ w1,
                          const float* __restrict__ w2, const float* __restrict__ w3) {
    int which = blockIdx.y;
    const float* src = which == 0 ? w0 : which == 1 ? w1 : which == 2 ? w2 : w3;
    int i = blockIdx.x * blockDim.x + threadIdx.x;       // float4 index
    if (i >= WELEM / 4) return;
    float4 v = ((const float4*)src)[i];
    uint32_t h0, l0, h1, l1;
    split2(v.x, v.y, h0, l0);
    split2(v.z, v.w, h1, l1);
    ((uint2*)g_w_hi[which])[i] = make_uint2(h0, h1);
    ((uint2*)g_w_lo[which])[i] = make_uint2(l0, l1);
}

// ---------------- message = relu(h_atom + bias), split to bf16 hi/lo ----------------
__global__ void k_message(const float* __restrict__ h_atom,
                          const float* __restrict__ bias, int n4) {
    int i = blockIdx.x * blockDim.x + threadIdx.x;
    if (i >= n4) return;
    float4 v = ((const float4*)h_atom)[i];
    float4 b = ((const float4*)bias)[i & (Hdim / 4 - 1)];
    v.x = fmaxf(v.x + b.x, 0.f);
    v.y = fmaxf(v.y + b.y, 0.f);
    v.z = fmaxf(v.z + b.z, 0.f);
    v.w = fmaxf(v.w + b.w, 0.f);
    uint32_t h0, l0, h1, l1;
    split2(v.x, v.y, h0, l0);
    split2(v.z, v.w, h1, l1);
    ((uint2*)g_msg_hi)[i] = make_uint2(h0, h1);
    ((uint2*)g_msg_lo)[i] = make_uint2(l0, l1);
}

// ---------------- h0 = segment max; write fp32 + bf16 hi/lo, both dirs ----------------
__global__ void k_h0(const float* __restrict__ h_atom) {
    int g = blockIdx.x;
    int c = threadIdx.x * 4;
    int s0 = g_start[g], s1 = g_start[g + 1];
    float4 m = make_float4(-3.4e38f, -3.4e38f, -3.4e38f, -3.4e38f);
    for (int r = s0; r < s1; r++) {
        float4 v = *(const float4*)&h_atom[(size_t)r * Hdim + c];
        m.x = fmaxf(m.x, v.x); m.y = fmaxf(m.y, v.y);
        m.z = fmaxf(m.z, v.z); m.w = fmaxf(m.w, v.w);
    }
    if (s1 == s0) m = make_float4(0.f, 0.f, 0.f, 0.f);
    uint32_t h0, l0, h1, l1;
    split2(m.x, m.y, h0, l0);
    split2(m.z, m.w, h1, l1);
    int fi = g * Hdim + c;
#pragma unroll
    for (int d = 0; d < 2; d++) {
        *(float4*)&g_h[d][0][fi] = m;
        ((uint2*)g_h_hi[d][0])[fi / 4 * 2 / 2] = make_uint2(h0, h1);  // fi/2 uints, uint2 index fi/4
        ((uint2*)g_h_lo[d][0])[fi / 4 * 2 / 2] = make_uint2(l0, l1);
    }
}

// =====================================================================
// Input GEMM (3x bf16): XG[n x 3072] = msg @ W_ih^T + b_ih
// Block 128m x 128n, K-chunk 16, 8 warps (2x4), warp 64x32.
// smem fragment-order: sA[buf][mfr8][lane32][reg4] (packed bf16x2),
//                      sB[buf][nfr16][lane32][reg2].
// =====================================================================
__global__ void __launch_bounds__(256) k_gemm_bf(
    const float* __restrict__ bi_f, const float* __restrict__ bi_b, int n)
{
    __shared__ uint32_t sAh[2048], sAl[2048], sBh[2048], sBl[2048];
    int dir = blockIdx.z;
    const uint32_t* Whi = g_w_hi[dir * 2];
    const uint32_t* Wlo = g_w_lo[dir * 2];
    const float* Bv = dir ? bi_b : bi_f;
    float* XG = g_xg[dir];
    int n0 = blockIdx.x * 128;
    int m0 = blockIdx.y * 128;
    int tid = threadIdx.x, lane = tid & 31, wid = tid >> 5;
    int wm = wid >> 2, wn = wid & 3;

    int ar = tid >> 1, ao = tid & 1;   // A slot: row 0..127, k-octet
    int br = tid >> 1, bo = tid & 1;   // B slot

    float acc[4][4][4];
#pragma unroll
    for (int m = 0; m < 4; m++)
#pragma unroll
        for (int q = 0; q < 4; q++)
#pragma unroll
            for (int e = 0; e < 4; e++) acc[m][q][e] = 0.f;

    uint4 pAh, pAl, pBh, pBl;

    auto ld = [&](int k0) {
        int rg = m0 + ar;
        int aidx = rg * (Hdim / 2) + (k0 + ao * 8) / 2;
        if (rg < n) {
            pAh = *(const uint4*)&g_msg_hi[aidx];
            pAl = *(const uint4*)&g_msg_lo[aidx];
        } else {
            pAh = make_uint4(0, 0, 0, 0); pAl = pAh;
        }
        size_t widx = (size_t)(n0 + br) * (Hdim / 2) + (k0 + bo * 8) / 2;
        pBh = *(const uint4*)&Whi[widx];
        pBl = *(const uint4*)&Wlo[widx];
    };
    auto st = [&](int buf) {
        int mfr = ar >> 4, rh = (ar >> 3) & 1, reg = ao * 2 + rh;
        int base = buf * 1024 + (mfr * 32 + (ar & 7) * 4) * 4 + reg;
        const uint32_t* ph = (const uint32_t*)&pAh;
        const uint32_t* pl = (const uint32_t*)&pAl;
#pragma unroll
        for (int p = 0; p < 4; p++) { sAh[base + p * 4] = ph[p]; sAl[base + p * 4] = pl[p]; }
        int nfr = br >> 3, nl = br & 7;
        int base2 = buf * 1024 + (nfr * 32 + nl * 4) * 2 + bo;
        const uint32_t* qh = (const uint32_t*)&pBh;
        const uint32_t* ql = (const uint32_t*)&pBl;
#pragma unroll
        for (int p = 0; p < 4; p++) { sBh[base2 + p * 2] = qh[p]; sBl[base2 + p * 2] = ql[p]; }
    };
    auto comp = [&](int buf) {
        uint4 ah[4], al[4]; uint2 bh[4], bl[4];
#pragma unroll
        for (int m = 0; m < 4; m++) {
            int base = buf * 1024 + ((wm * 4 + m) * 32 + lane) * 4;
            ah[m] = *(const uint4*)&sAh[base];
            al[m] = *(const uint4*)&sAl[base];
        }
#pragma unroll
        for (int q = 0; q < 4; q++) {
            int base = buf * 1024 + ((wn * 4 + q) * 32 + lane) * 2;
            bh[q] = *(const uint2*)&sBh[base];
            bl[q] = *(const uint2*)&sBl[base];
        }
#pragma unroll
        for (int m = 0; m < 4; m++)
#pragma unroll
            for (int q = 0; q < 4; q++) {
                mma16(acc[m][q], (const uint32_t*)&ah[m], (const uint32_t*)&bh[q]);
                mma16(acc[m][q], (const uint32_t*)&al[m], (const uint32_t*)&bh[q]);
                mma16(acc[m][q], (const uint32_t*)&ah[m], (const uint32_t*)&bl[q]);
            }
    };

    ld(0); st(0); __syncthreads();
    for (int c = 0; c < Hdim / 16; c++) {
        int buf = c & 1;
        if (c + 1 < Hdim / 16) ld((c + 1) * 16);
        comp(buf);
        if (c + 1 < Hdim / 16) { st(buf ^ 1); __syncthreads(); }
    }

#pragma unroll
    for (int m = 0; m < 4; m++)
#pragma unroll
        for (int half = 0; half < 2; half++) {
            int row = m0 + wm * 64 + m * 16 + (lane >> 2) + half * 8;
            if (row < n) {
#pragma unroll
                for (int q = 0; q < 4; q++) {
                    int col = n0 + wn * 32 + q * 8 + (lane & 3) * 2;
                    float2 o;
                    o.x = acc[m][q][half * 2 + 0] + Bv[col];
                    o.y = acc[m][q][half * 2 + 1] + Bv[col + 1];
                    *(float2*)&XG[(size_t)row * H3 + col] = o;
                }
            }
        }
}

// =====================================================================
// GRU step (3x bf16): gates = h @ W_hh^T + fused epilogue.
// Block 64g x 192n (64 j-cols x 3 gates), K-chunk 16, 8 warps.
// Warp w owns j-frag w across all 3 gates: nfr {w, 8+w, 16+w}.
// =====================================================================
__global__ void __launch_bounds__(256) k_step_bf(
    const float* __restrict__ bhh_f, const float* __restrict__ bih_f,
    const float* __restrict__ bhh_b, const float* __restrict__ bih_b,
    float* __restrict__ out, int s)
{
    __shared__ uint32_t sAh[1024], sAl[1024], sBh[3072], sBl[3072];
    int dir = blockIdx.z;
    const uint32_t* Whi = g_w_hi[dir * 2 + 1];
    const uint32_t* Wlo = g_w_lo[dir * 2 + 1];
    const float* Bh = dir ? bhh_b : bhh_f;
    const float* Bi = dir ? bih_b : bih_f;
    const float* xg = g_xg[dir];
    int par = s & 1;
    const float*    hin  = g_h[dir][par];
    float*          hout = g_h[dir][par ^ 1];
    const uint32_t* hhi  = g_h_hi[dir][par];
    const uint32_t* hlo  = g_h_lo[dir][par];
    uint32_t*       hohi = g_h_hi[dir][par ^ 1];
    uint32_t*       holo = g_h_lo[dir][par ^ 1];
    int tstep = dir ? (Ldim - 1 - s) : s;

    int j0 = blockIdx.x * 64;
    int g0 = blockIdx.y * 64;
    int tid = threadIdx.x, lane = tid & 31, w = tid >> 5;

    bool hasA = tid < 128;
    int ar = tid >> 1, ao = tid & 1;            // A slot (hasA): row 0..63
    int b1nr = tid >> 1, b1o = tid & 1;         // B slot: nr 0..127
    int b2nr = 128 + (tid >> 1), b2o = tid & 1; // B slot (hasA): nr 128..191

    float acc[4][3][4];
#pragma unroll
    for (int m = 0; m < 4; m++)
#pragma unroll
        for (int q = 0; q < 3; q++)
#pragma unroll
            for (int e = 0; e < 4; e++) acc[m][q][e] = 0.f;

    uint4 pAh, pAl, pB1h, pB1l, pB2h, pB2l;

    auto wrow = [&](int nr) { int gate = nr >> 6, jl = nr & 63; return gate * Hdim + j0 + jl; };

    auto ld = [&](int k0) {
        if (hasA) {
            int idx = (g0 + ar) * (Hdim / 2) + (k0 + ao * 8) / 2;
            pAh = *(const uint4*)&hhi[idx];
            pAl = *(const uint4*)&hlo[idx];
            size_t wi2 = (size_t)wrow(b2nr) * (Hdim / 2) + (k0 + b2o * 8) / 2;
            pB2h = *(const uint4*)&Whi[wi2];
            pB2l = *(const uint4*)&Wlo[wi2];
        }
        size_t wi1 = (size_t)wrow(b1nr) * (Hdim / 2) + (k0 + b1o * 8) / 2;
        pB1h = *(const uint4*)&Whi[wi1];
        pB1l = *(const uint4*)&Wlo[wi1];
    };
    auto st = [&](int buf) {
        if (hasA) {
            int mfr = ar >> 4, rh = (ar >> 3) & 1, reg = ao * 2 + rh;
            int base = buf * 512 + (mfr * 32 + (ar & 7) * 4) * 4 + reg;
            const uint32_t* ph = (const uint32_t*)&pAh;
            const uint32_t* pl = (const uint32_t*)&pAl;
#pragma unroll
            for (int p = 0; p < 4; p++) { sAh[base + p * 4] = ph[p]; sAl[base + p * 4] = pl[p]; }
            int nfr2 = b2nr >> 3, nl2 = b2nr & 7;
            int base2 = buf * 1536 + (nfr2 * 32 + nl2 * 4) * 2 + b2o;
            const uint32_t* qh = (const uint32_t*)&pB2h;
            const uint32_t* ql = (const uint32_t*)&pB2l;
#pragma unroll
            for (int p = 0; p < 4; p++) { sBh[base2 + p * 2] = qh[p]; sBl[base2 + p * 2] = ql[p]; }
        }
        int nfr1 = b1nr >> 3, nl1 = b1nr & 7;
        int base1 = buf * 1536 + (nfr1 * 32 + nl1 * 4) * 2 + b1o;
        const uint32_t* rh2 = (const uint32_t*)&pB1h;
        const uint32_t* rl2 = (const uint32_t*)&pB1l;
#pragma unroll
        for (int p = 0; p < 4; p++) { sBh[base1 + p * 2] = rh2[p]; sBl[base1 + p * 2] = rl2[p]; }
    };
    auto comp = [&](int buf) {
        uint4 ah[4], al[4]; uint2 bh[3], bl[3];
#pragma unroll
        for (int m = 0; m < 4; m++) {
            int base = buf * 512 + (m * 32 + lane) * 4;
            ah[m] = *(const uint4*)&sAh[base];
            al[m] = *(const uint4*)&sAl[base];
        }
#pragma unroll
        for (int q = 0; q < 3; q++) {
            int nfr = q * 8 + w;
            int base = buf * 1536 + (nfr * 32 + lane) * 2;
            bh[q] = *(const uint2*)&sBh[base];
            bl[q] = *(const uint2*)&sBl[base];
        }
#pragma unroll
        for (int m = 0; m < 4; m++)
#pragma unroll
            for (int q = 0; q < 3; q++) {
                mma16(acc[m][q], (const uint32_t*)&ah[m], (const uint32_t*)&bh[q]);
                mma16(acc[m][q], (const uint32_t*)&al[m], (const uint32_t*)&bh[q]);
                mma16(acc[m][q], (const uint32_t*)&ah[m], (const uint32_t*)&bl[q]);
            }
    };

    ld(0); st(0); __syncthreads();
    for (int c = 0; c < Hdim / 16; c++) {
        int buf = c & 1;
        if (c + 1 < Hdim / 16) ld((c + 1) * 16);
        comp(buf);
        if (c + 1 < Hdim / 16) { st(buf ^ 1); __syncthreads(); }
    }

    // ---- fused gate epilogue + h split + scatter ----
#pragma unroll
    for (int m = 0; m < 4; m++) {
#pragma unroll
        for (int half = 0; half < 2; half++) {
            int g = g0 + m * 16 + (lane >> 2) + half * 8;
            int stt = g_start[g];
            int cnt = g_start[g + 1] - stt;
            bool valid = (tstep < cnt);
            size_t abase = (size_t)(stt + tstep) * H3;
            int j = j0 + w * 8 + (lane & 3) * 2;
            float hn2[2];
#pragma unroll
            for (int cp = 0; cp < 2; cp++) {
                int jj = j + cp;
                float xr, xz, xn;
                if (valid) {
                    xr = xg[abase + jj];
                    xz = xg[abase + Hdim + jj];
                    xn = xg[abase + 2 * Hdim + jj];
                } else {
                    xr = Bi[jj]; xz = Bi[Hdim + jj]; xn = Bi[2 * Hdim + jj];
                }
                int e = half * 2 + cp;
                float r  = 1.f / (1.f + expf(-(xr + acc[m][0][e] + Bh[jj])));
                float z  = 1.f / (1.f + expf(-(xz + acc[m][1][e] + Bh[Hdim + jj])));
                float nn = tanhf(xn + r * (acc[m][2][e] + Bh[2 * Hdim + jj]));
                float hp = hin[g * Hdim + jj];
                float hv = (1.f - z) * nn + z * hp;
                hout[g * Hdim + jj] = hv;
                hn2[cp] = hv;
                if (valid)
                    out[(size_t)(stt + tstep) * (2 * Hdim) + dir * Hdim + jj] = hv;
            }
            uint32_t hh, ll;
            split2(hn2[0], hn2[1], hh, ll);
            hohi[(g * Hdim + j) / 2] = hh;
            holo[(g * Hdim + j) / 2] = ll;
        }
    }
}

// ---------------- host launcher ----------------
extern "C" void kernel_launch(void* const* d_in, const int* in_sizes, int n_in,
                              void* d_out, int out_size)
{
    int nAtoms = in_sizes[0] / Hdim;

    const float* h_atom = (const float*)d_in[0];
    int iBatch, iBias, iWihF, iWhhF, iBihF, iBhhF, iWihB, iWhhB, iBihB, iBhhB;
    if (in_sizes[1] == nAtoms) {
        iBatch = 1; iBias = 2; iWihF = 3; iWhhF = 4; iBihF = 5; iBhhF = 6;
        iWihB = 7; iWhhB = 8; iBihB = 9; iBhhB = 10;
    } else {
        iBias = 1; iWihF = 2; iWhhF = 3; iBihF = 4; iBhhF = 5;
        iWihB = 6; iWhhB = 7; iBihB = 8; iBhhB = 9; iBatch = 10;
    }

    const int*   batch = (const int*)d_in[iBatch];
    const float* bias  = (const float*)d_in[iBias];
    const float* wihf  = (const float*)d_in[iWihF];
    const float* whhf  = (const float*)d_in[iWhhF];
    const float* bihf  = (const float*)d_in[iBihF];
    const float* bhhf  = (const float*)d_in[iBhhF];
    const float* wihb  = (const float*)d_in[iWihB];
    const float* whhb  = (const float*)d_in[iWhhB];
    const float* bihb  = (const float*)d_in[iBihB];
    const float* bhhb  = (const float*)d_in[iBhhB];
    float* out = (float*)d_out;

    k_meta<<<1, 512>>>(batch, nAtoms);

    dim3 gw(WELEM / 4 / 256, 4);
    k_split_w<<<gw, 256>>>(wihf, whhf, wihb, whhb);

    int n4 = nAtoms * Hdim / 4;
    k_message<<<(n4 + 255) / 256, 256>>>(h_atom, bias, n4);

    k_h0<<<Gdim, 256>>>(h_atom);

    dim3 gg(H3 / 128, (nAtoms + 127) / 128, 2);
    k_gemm_bf<<<gg, 256>>>(bihf, bihb, nAtoms);

    dim3 gs(Hdim / 64, Gdim / 64, 2);
    for (int s = 0; s < Ldim; s++) {
        k_step_bf<<<gs, 256>>>(bhhf, bihf, bhhb, bihb, out, s);
    }
}

// round 5
// speedup vs baseline: 2.1888x; 1.2248x over previous
#include <cuda_runtime.h>
#include <cuda_fp16.h>
#include <math.h>
#include <stdint.h>

#define Hdim 1024
#define H3   3072
#define Gdim 256
#define Ldim 128
#define NMAX 16384
#define WELEM (H3 * Hdim)

// ---------------- scratch (device globals; no allocations) ----------------
__device__ uint32_t g_msg16[NMAX * Hdim / 2];        // fp16x2 rounded message
__device__ uint32_t g_w16h[4][WELEM / 2];            // fp16x2 weight hi: 0=ih_f 1=hh_f 2=ih_b 3=hh_b
__device__ uint32_t g_w16l[4][WELEM / 2];            // fp16x2 weight lo
__device__ float    g_xg[2][(size_t)NMAX * H3];
__device__ float    g_h[2][2][Gdim * Hdim];          // fp32 hidden (exact carry)
__device__ uint32_t g_h16[2][2][Gdim * Hdim / 2];    // fp16x2 rounded hidden (mma operand)
__device__ int      g_start[Gdim + 1];

// ---------------- helpers ----------------
__device__ __forceinline__ uint32_t pack2h(float x, float y) {
    __half2 h = __halves2half2(__float2half_rn(x), __float2half_rn(y));
    return *reinterpret_cast<uint32_t*>(&h);
}
__device__ __forceinline__ void split2h(float x, float y, uint32_t& hi, uint32_t& lo) {
    __half hx = __float2half_rn(x), hy = __float2half_rn(y);
    __half lx = __float2half_rn(x - __half2float(hx));
    __half ly = __float2half_rn(y - __half2float(hy));
    __half2 h = __halves2half2(hx, hy);
    __half2 l = __halves2half2(lx, ly);
    hi = *reinterpret_cast<uint32_t*>(&h);
    lo = *reinterpret_cast<uint32_t*>(&l);
}
__device__ __forceinline__ void mma16f(float* d, const uint32_t* a, const uint32_t* b) {
    asm volatile(
        "mma.sync.aligned.m16n8k16.row.col.f32.f16.f16.f32 "
        "{%0,%1,%2,%3}, {%4,%5,%6,%7}, {%8,%9}, {%0,%1,%2,%3};\n"
        : "+f"(d[0]), "+f"(d[1]), "+f"(d[2]), "+f"(d[3])
        : "r"(a[0]), "r"(a[1]), "r"(a[2]), "r"(a[3]), "r"(b[0]), "r"(b[1]));
}

// ---------------- meta: segment starts ----------------
__global__ void k_meta(const int* __restrict__ batch, int n) {
    int g = threadIdx.x;
    if (g > Gdim) return;
    int lo = 0, hi = n;
    while (lo < hi) {
        int mid = (lo + hi) >> 1;
        if (batch[mid] < g) lo = mid + 1; else hi = mid;
    }
    g_start[g] = lo;
}

// ---------------- weight pre-split (fp32 -> fp16 hi/lo) ----------------
__global__ void k_split_w(const float* __restrict__ w0, const float* __restrict__ w1,
                          const float* __restrict__ w2, const float* __restrict__ w3) {
    int which = blockIdx.y;
    const float* src = which == 0 ? w0 : which == 1 ? w1 : which == 2 ? w2 : w3;
    int i = blockIdx.x * blockDim.x + threadIdx.x;
    if (i >= WELEM / 4) return;
    float4 v = ((const float4*)src)[i];
    uint32_t h0, l0, h1, l1;
    split2h(v.x, v.y, h0, l0);
    split2h(v.z, v.w, h1, l1);
    ((uint2*)g_w16h[which])[i] = make_uint2(h0, h1);
    ((uint2*)g_w16l[which])[i] = make_uint2(l0, l1);
}

// ---------------- message = relu(h_atom + bias) -> fp16 ----------------
__global__ void k_message(const float* __restrict__ h_atom,
                          const float* __restrict__ bias, int n4) {
    int i = blockIdx.x * blockDim.x + threadIdx.x;
    if (i >= n4) return;
    float4 v = ((const float4*)h_atom)[i];
    float4 b = ((const float4*)bias)[i & (Hdim / 4 - 1)];
    v.x = fmaxf(v.x + b.x, 0.f);
    v.y = fmaxf(v.y + b.y, 0.f);
    v.z = fmaxf(v.z + b.z, 0.f);
    v.w = fmaxf(v.w + b.w, 0.f);
    ((uint2*)g_msg16)[i] = make_uint2(pack2h(v.x, v.y), pack2h(v.z, v.w));
}

// ---------------- h0 = segment max; fp32 + fp16, both dirs ----------------
__global__ void k_h0(const float* __restrict__ h_atom) {
    int g = blockIdx.x;
    int c = threadIdx.x * 4;
    int s0 = g_start[g], s1 = g_start[g + 1];
    float4 m = make_float4(-3.4e38f, -3.4e38f, -3.4e38f, -3.4e38f);
    for (int r = s0; r < s1; r++) {
        float4 v = *(const float4*)&h_atom[(size_t)r * Hdim + c];
        m.x = fmaxf(m.x, v.x); m.y = fmaxf(m.y, v.y);
        m.z = fmaxf(m.z, v.z); m.w = fmaxf(m.w, v.w);
    }
    if (s1 == s0) m = make_float4(0.f, 0.f, 0.f, 0.f);
    int fi = g * Hdim + c;
    uint2 p = make_uint2(pack2h(m.x, m.y), pack2h(m.z, m.w));
#pragma unroll
    for (int d = 0; d < 2; d++) {
        *(float4*)&g_h[d][0][fi] = m;
        ((uint2*)g_h16[d][0])[fi / 4] = p;
    }
}

// =====================================================================
// Input GEMM (fp16-2): XG[n x 3072] = msg @ W_ih^T + b_ih
// Block 128m x 128n, K-chunk 16, 8 warps (2m x 4n), warp 64x32.
// smem fragment-order: sA[buf][mfr8][lane32][reg4],
//                      sB{h,l}[buf][nfr16][lane32][reg2].
// =====================================================================
__global__ void __launch_bounds__(256) k_gemm_f16(
    const float* __restrict__ bi_f, const float* __restrict__ bi_b, int n)
{
    __shared__ uint32_t sA[2048], sBh[2048], sBl[2048];
    int dir = blockIdx.z;
    const uint32_t* Whi = g_w16h[dir * 2];
    const uint32_t* Wlo = g_w16l[dir * 2];
    const float* Bv = dir ? bi_b : bi_f;
    float* XG = g_xg[dir];
    int n0 = blockIdx.x * 128;
    int m0 = blockIdx.y * 128;
    int tid = threadIdx.x, lane = tid & 31, wid = tid >> 5;
    int wm = wid >> 2, wn = wid & 3;

    int ar = tid >> 1, ao = tid & 1;   // A: 128 rows x 2 k-octets
    int br = tid >> 1, bo = tid & 1;   // B: 128 rows x 2 k-octets

    float acc[4][4][4];
#pragma unroll
    for (int m = 0; m < 4; m++)
#pragma unroll
        for (int q = 0; q < 4; q++)
#pragma unroll
            for (int e = 0; e < 4; e++) acc[m][q][e] = 0.f;

    uint4 pA, pBh, pBl;

    auto ld = [&](int k0) {
        int rg = m0 + ar;
        if (rg < n) pA = *(const uint4*)&g_msg16[rg * (Hdim / 2) + (k0 + ao * 8) / 2];
        else        pA = make_uint4(0, 0, 0, 0);
        size_t widx = (size_t)(n0 + br) * (Hdim / 2) + (k0 + bo * 8) / 2;
        pBh = *(const uint4*)&Whi[widx];
        pBl = *(const uint4*)&Wlo[widx];
    };
    auto st = [&](int buf) {
        int mfr = ar >> 4, rh = (ar >> 3) & 1, reg = ao * 2 + rh;
        int base = buf * 1024 + (mfr * 32 + (ar & 7) * 4) * 4 + reg;
        const uint32_t* p = (const uint32_t*)&pA;
#pragma unroll
        for (int i = 0; i < 4; i++) sA[base + i * 4] = p[i];
        int nfr = br >> 3, nl = br & 7;
        int base2 = buf * 1024 + (nfr * 32 + nl * 4) * 2 + bo;
        const uint32_t* qh = (const uint32_t*)&pBh;
        const uint32_t* ql = (const uint32_t*)&pBl;
#pragma unroll
        for (int i = 0; i < 4; i++) { sBh[base2 + i * 2] = qh[i]; sBl[base2 + i * 2] = ql[i]; }
    };
    auto comp = [&](int buf) {
        uint4 a[4]; uint2 bh[4], bl[4];
#pragma unroll
        for (int m = 0; m < 4; m++)
            a[m] = *(const uint4*)&sA[buf * 1024 + ((wm * 4 + m) * 32 + lane) * 4];
#pragma unroll
        for (int q = 0; q < 4; q++) {
            int base = buf * 1024 + ((wn * 4 + q) * 32 + lane) * 2;
            bh[q] = *(const uint2*)&sBh[base];
            bl[q] = *(const uint2*)&sBl[base];
        }
#pragma unroll
        for (int m = 0; m < 4; m++)
#pragma unroll
            for (int q = 0; q < 4; q++) {
                mma16f(acc[m][q], (const uint32_t*)&a[m], (const uint32_t*)&bh[q]);
                mma16f(acc[m][q], (const uint32_t*)&a[m], (const uint32_t*)&bl[q]);
            }
    };

    ld(0); st(0); __syncthreads();
    for (int c = 0; c < Hdim / 16; c++) {
        int buf = c & 1;
        if (c + 1 < Hdim / 16) ld((c + 1) * 16);
        comp(buf);
        if (c + 1 < Hdim / 16) { st(buf ^ 1); __syncthreads(); }
    }

#pragma unroll
    for (int m = 0; m < 4; m++)
#pragma unroll
        for (int half = 0; half < 2; half++) {
            int row = m0 + wm * 64 + m * 16 + (lane >> 2) + half * 8;
            if (row < n) {
#pragma unroll
                for (int q = 0; q < 4; q++) {
                    int col = n0 + wn * 32 + q * 8 + (lane & 3) * 2;
                    float2 o;
                    o.x = acc[m][q][half * 2 + 0] + Bv[col];
                    o.y = acc[m][q][half * 2 + 1] + Bv[col + 1];
                    *(float2*)&XG[(size_t)row * H3 + col] = o;
                }
            }
        }
}

// =====================================================================
// GRU step (fp16-2): gates = h @ W_hh^T + fused epilogue.
// Block 64g x 96n (32 j x 3 gates), K-chunk 16, 8 warps (2m x 4n).
// grid (32 jtiles, 4 gtiles, 2 dirs) = 256 CTAs -> 2/SM.
// Warp wn owns j-octet wn across all 3 gates: nfr {wn, 4+wn, 8+wn}.
// =====================================================================
__global__ void __launch_bounds__(256, 2) k_step_f16(
    const float* __restrict__ bhh_f, const float* __restrict__ bih_f,
    const float* __restrict__ bhh_b, const float* __restrict__ bih_b,
    float* __restrict__ out, int s)
{
    __shared__ uint32_t sA[1024], sBh[1536], sBl[1536];
    int dir = blockIdx.z;
    const uint32_t* Whi = g_w16h[dir * 2 + 1];
    const uint32_t* Wlo = g_w16l[dir * 2 + 1];
    const float* Bh = dir ? bhh_b : bhh_f;
    const float* Bi = dir ? bih_b : bih_f;
    const float* xg = g_xg[dir];
    int par = s & 1;
    const float*    hin  = g_h[dir][par];
    float*          hout = g_h[dir][par ^ 1];
    const uint32_t* h16  = g_h16[dir][par];
    uint32_t*       ho16 = g_h16[dir][par ^ 1];
    int tstep = dir ? (Ldim - 1 - s) : s;

    int j0 = blockIdx.x * 32;
    int g0 = blockIdx.y * 64;
    int tid = threadIdx.x, lane = tid & 31, wid = tid >> 5;
    int wm = wid >> 2, wn = wid & 3;

    bool hasA = tid < 128;
    int arow = tid >> 1, ao = tid & 1;     // A: 64 rows x 2 octets (tid<128)
    bool hasB = tid < 192;
    int brow = tid >> 1, bo = tid & 1;     // B: 96 rows x 2 octets (tid<192)
    int wrowB = 0;
    if (hasB) {
        int gate = brow >> 5, jl = brow & 31;
        wrowB = gate * Hdim + j0 + jl;
    }

    float acc[2][3][4];
#pragma unroll
    for (int m = 0; m < 2; m++)
#pragma unroll
        for (int gt = 0; gt < 3; gt++)
#pragma unroll
            for (int e = 0; e < 4; e++) acc[m][gt][e] = 0.f;

    uint4 pA, pBh, pBl;

    auto ld = [&](int k0) {
        if (hasA)
            pA = *(const uint4*)&h16[(g0 + arow) * (Hdim / 2) + (k0 + ao * 8) / 2];
        if (hasB) {
            size_t widx = (size_t)wrowB * (Hdim / 2) + (k0 + bo * 8) / 2;
            pBh = *(const uint4*)&Whi[widx];
            pBl = *(const uint4*)&Wlo[widx];
        }
    };
    auto st = [&](int buf) {
        if (hasA) {
            int mfr = arow >> 4, rh = (arow >> 3) & 1, reg = ao * 2 + rh;
            int base = buf * 512 + (mfr * 32 + (arow & 7) * 4) * 4 + reg;
            const uint32_t* p = (const uint32_t*)&pA;
#pragma unroll
            for (int i = 0; i < 4; i++) sA[base + i * 4] = p[i];
        }
        if (hasB) {
            int nfr = brow >> 3, nl = brow & 7;
            int base = buf * 768 + (nfr * 32 + nl * 4) * 2 + bo;
            const uint32_t* qh = (const uint32_t*)&pBh;
            const uint32_t* ql = (const uint32_t*)&pBl;
#pragma unroll
            for (int i = 0; i < 4; i++) { sBh[base + i * 2] = qh[i]; sBl[base + i * 2] = ql[i]; }
        }
    };
    auto comp = [&](int buf) {
        uint4 a[2]; uint2 bh[3], bl[3];
#pragma unroll
        for (int m = 0; m < 2; m++)
            a[m] = *(const uint4*)&sA[buf * 512 + ((wm * 2 + m) * 32 + lane) * 4];
#pragma unroll
        for (int gt = 0; gt < 3; gt++) {
            int base = buf * 768 + ((gt * 4 + wn) * 32 + lane) * 2;
            bh[gt] = *(const uint2*)&sBh[base];
            bl[gt] = *(const uint2*)&sBl[base];
        }
#pragma unroll
        for (int m = 0; m < 2; m++)
#pragma unroll
            for (int gt = 0; gt < 3; gt++) {
                mma16f(acc[m][gt], (const uint32_t*)&a[m], (const uint32_t*)&bh[gt]);
                mma16f(acc[m][gt], (const uint32_t*)&a[m], (const uint32_t*)&bl[gt]);
            }
    };

    ld(0); st(0); __syncthreads();
    for (int c = 0; c < Hdim / 16; c++) {
        int buf = c & 1;
        if (c + 1 < Hdim / 16) ld((c + 1) * 16);
        comp(buf);
        if (c + 1 < Hdim / 16) { st(buf ^ 1); __syncthreads(); }
    }

    // ---- fused gate epilogue + fp16 round + scatter ----
#pragma unroll
    for (int m = 0; m < 2; m++) {
#pragma unroll
        for (int half = 0; half < 2; half++) {
            int g = g0 + (wm * 2 + m) * 16 + (lane >> 2) + half * 8;
            int stt = g_start[g];
            int cnt = g_start[g + 1] - stt;
            bool valid = (tstep < cnt);
            size_t abase = (size_t)(stt + tstep) * H3;
            int j = j0 + wn * 8 + (lane & 3) * 2;
            float hv[2];
#pragma unroll
            for (int cp = 0; cp < 2; cp++) {
                int jj = j + cp;
                float xr, xz, xn;
                if (valid) {
                    xr = xg[abase + jj];
                    xz = xg[abase + Hdim + jj];
                    xn = xg[abase + 2 * Hdim + jj];
                } else {
                    xr = Bi[jj]; xz = Bi[Hdim + jj]; xn = Bi[2 * Hdim + jj];
                }
                int e = half * 2 + cp;
                float r  = 1.f / (1.f + expf(-(xr + acc[m][0][e] + Bh[jj])));
                float z  = 1.f / (1.f + expf(-(xz + acc[m][1][e] + Bh[Hdim + jj])));
                float nn = tanhf(xn + r * (acc[m][2][e] + Bh[2 * Hdim + jj]));
                float hp = hin[g * Hdim + jj];
                hv[cp] = (1.f - z) * nn + z * hp;
                hout[g * Hdim + jj] = hv[cp];
                if (valid)
                    out[(size_t)(stt + tstep) * (2 * Hdim) + (size_t)dir * Hdim + jj] = hv[cp];
            }
            ho16[(g * Hdim + j) / 2] = pack2h(hv[0], hv[1]);
        }
    }
}

// ---------------- host launcher ----------------
extern "C" void kernel_launch(void* const* d_in, const int* in_sizes, int n_in,
                              void* d_out, int out_size)
{
    int nAtoms = in_sizes[0] / Hdim;

    const float* h_atom = (const float*)d_in[0];
    int iBatch, iBias, iWihF, iWhhF, iBihF, iBhhF, iWihB, iWhhB, iBihB, iBhhB;
    if (in_sizes[1] == nAtoms) {
        iBatch = 1; iBias = 2; iWihF = 3; iWhhF = 4; iBihF = 5; iBhhF = 6;
        iWihB = 7; iWhhB = 8; iBihB = 9; iBhhB = 10;
    } else {
        iBias = 1; iWihF = 2; iWhhF = 3; iBihF = 4; iBhhF = 5;
        iWihB = 6; iWhhB = 7; iBihB = 8; iBhhB = 9; iBatch = 10;
    }

    const int*   batch = (const int*)d_in[iBatch];
    const float* bias  = (const float*)d_in[iBias];
    const float* wihf  = (const float*)d_in[iWihF];
    const float* whhf  = (const float*)d_in[iWhhF];
    const float* bihf  = (const float*)d_in[iBihF];
    const float* bhhf  = (const float*)d_in[iBhhF];
    const float* wihb  = (const float*)d_in[iWihB];
    const float* whhb  = (const float*)d_in[iWhhB];
    const float* bihb  = (const float*)d_in[iBihB];
    const float* bhhb  = (const float*)d_in[iBhhB];
    float* out = (float*)d_out;

    k_meta<<<1, 512>>>(batch, nAtoms);

    dim3 gw(WELEM / 4 / 256, 4);
    k_split_w<<<gw, 256>>>(wihf, whhf, wihb, whhb);

    int n4 = nAtoms * Hdim / 4;
    k_message<<<(n4 + 255) / 256, 256>>>(h_atom, bias, n4);

    k_h0<<<Gdim, 256>>>(h_atom);

    dim3 gg(H3 / 128, (nAtoms + 127) / 128, 2);
    k_gemm_f16<<<gg, 256>>>(bihf, bihb, nAtoms);

    dim3 gs(Hdim / 32, Gdim / 64, 2);
    for (int s = 0; s < Ldim; s++) {
        k_step_f16<<<gs, 256>>>(bhhf, bihf, bhhb, bihb, out, s);
    }
}

// round 6
// speedup vs baseline: 3.0291x; 1.3839x over previous
#include <cuda_runtime.h>
#include <cuda_fp16.h>
#include <math.h>
#include <stdint.h>

#define Hdim 1024
#define H3   3072
#define Gdim 256
#define Ldim 128
#define NMAX 16384
#define WELEM (H3 * Hdim)

// ---------------- scratch (device globals; no allocations) ----------------
__device__ uint32_t g_msg16[NMAX * Hdim / 2];        // fp16x2 rounded message
__device__ uint32_t g_w16[4][WELEM / 2];             // fp16x2 weights: 0=ih_f 1=hh_f 2=ih_b 3=hh_b
__device__ float    g_xg[2][(size_t)NMAX * H3];
__device__ float    g_h[2][2][Gdim * Hdim];          // fp32 hidden (exact carry)
__device__ uint32_t g_h16[2][2][Gdim * Hdim / 2];    // fp16x2 rounded hidden (mma operand)
__device__ int      g_start[Gdim + 1];

// ---------------- helpers ----------------
__device__ __forceinline__ uint32_t pack2h(float x, float y) {
    __half2 h = __halves2half2(__float2half_rn(x), __float2half_rn(y));
    return *reinterpret_cast<uint32_t*>(&h);
}
__device__ __forceinline__ void mma16f(float* d, const uint32_t* a, const uint32_t* b) {
    asm volatile(
        "mma.sync.aligned.m16n8k16.row.col.f32.f16.f16.f32 "
        "{%0,%1,%2,%3}, {%4,%5,%6,%7}, {%8,%9}, {%0,%1,%2,%3};\n"
        : "+f"(d[0]), "+f"(d[1]), "+f"(d[2]), "+f"(d[3])
        : "r"(a[0]), "r"(a[1]), "r"(a[2]), "r"(a[3]), "r"(b[0]), "r"(b[1]));
}

// ---------------- meta: segment starts ----------------
__global__ void k_meta(const int* __restrict__ batch, int n) {
    int g = threadIdx.x;
    if (g > Gdim) return;
    int lo = 0, hi = n;
    while (lo < hi) {
        int mid = (lo + hi) >> 1;
        if (batch[mid] < g) lo = mid + 1; else hi = mid;
    }
    g_start[g] = lo;
}

// ---------------- weight round (fp32 -> fp16) ----------------
__global__ void k_round_w(const float* __restrict__ w0, const float* __restrict__ w1,
                          const float* __restrict__ w2, const float* __restrict__ w3) {
    int which = blockIdx.y;
    const float* src = which == 0 ? w0 : which == 1 ? w1 : which == 2 ? w2 : w3;
    int i = blockIdx.x * blockDim.x + threadIdx.x;
    if (i >= WELEM / 4) return;
    float4 v = ((const float4*)src)[i];
    ((uint2*)g_w16[which])[i] = make_uint2(pack2h(v.x, v.y), pack2h(v.z, v.w));
}

// ---------------- message = relu(h_atom + bias) -> fp16 ----------------
__global__ void k_message(const float* __restrict__ h_atom,
                          const float* __restrict__ bias, int n4) {
    int i = blockIdx.x * blockDim.x + threadIdx.x;
    if (i >= n4) return;
    float4 v = ((const float4*)h_atom)[i];
    float4 b = ((const float4*)bias)[i & (Hdim / 4 - 1)];
    v.x = fmaxf(v.x + b.x, 0.f);
    v.y = fmaxf(v.y + b.y, 0.f);
    v.z = fmaxf(v.z + b.z, 0.f);
    v.w = fmaxf(v.w + b.w, 0.f);
    ((uint2*)g_msg16)[i] = make_uint2(pack2h(v.x, v.y), pack2h(v.z, v.w));
}

// ---------------- h0 = segment max; fp32 + fp16, both dirs ----------------
__global__ void k_h0(const float* __restrict__ h_atom) {
    int g = blockIdx.x;
    int c = threadIdx.x * 4;
    int s0 = g_start[g], s1 = g_start[g + 1];
    float4 m = make_float4(-3.4e38f, -3.4e38f, -3.4e38f, -3.4e38f);
    for (int r = s0; r < s1; r++) {
        float4 v = *(const float4*)&h_atom[(size_t)r * Hdim + c];
        m.x = fmaxf(m.x, v.x); m.y = fmaxf(m.y, v.y);
        m.z = fmaxf(m.z, v.z); m.w = fmaxf(m.w, v.w);
    }
    if (s1 == s0) m = make_float4(0.f, 0.f, 0.f, 0.f);
    int fi = g * Hdim + c;
    uint2 p = make_uint2(pack2h(m.x, m.y), pack2h(m.z, m.w));
#pragma unroll
    for (int d = 0; d < 2; d++) {
        *(float4*)&g_h[d][0][fi] = m;
        ((uint2*)g_h16[d][0])[fi / 4] = p;
    }
}

// =====================================================================
// Input GEMM (fp16): XG[n x 3072] = msg @ W_ih^T + b_ih
// Block 128m x 128n, K-chunk 16, 8 warps (2m x 4n), warp 64x32.
// =====================================================================
__global__ void __launch_bounds__(256) k_gemm_f16(
    const float* __restrict__ bi_f, const float* __restrict__ bi_b, int n)
{
    __shared__ uint32_t sA[2048], sB[2048];
    int dir = blockIdx.z;
    const uint32_t* W = g_w16[dir * 2];
    const float* Bv = dir ? bi_b : bi_f;
    float* XG = g_xg[dir];
    int n0 = blockIdx.x * 128;
    int m0 = blockIdx.y * 128;
    int tid = threadIdx.x, lane = tid & 31, wid = tid >> 5;
    int wm = wid >> 2, wn = wid & 3;

    int ar = tid >> 1, ao = tid & 1;
    int br = tid >> 1, bo = tid & 1;

    float acc[4][4][4];
#pragma unroll
    for (int m = 0; m < 4; m++)
#pragma unroll
        for (int q = 0; q < 4; q++)
#pragma unroll
            for (int e = 0; e < 4; e++) acc[m][q][e] = 0.f;

    uint4 pA, pB;

    auto ld = [&](int k0) {
        int rg = m0 + ar;
        if (rg < n) pA = *(const uint4*)&g_msg16[rg * (Hdim / 2) + (k0 + ao * 8) / 2];
        else        pA = make_uint4(0, 0, 0, 0);
        pB = *(const uint4*)&W[(size_t)(n0 + br) * (Hdim / 2) + (k0 + bo * 8) / 2];
    };
    auto st = [&](int buf) {
        int mfr = ar >> 4, rh = (ar >> 3) & 1, reg = ao * 2 + rh;
        int base = buf * 1024 + (mfr * 32 + (ar & 7) * 4) * 4 + reg;
        const uint32_t* p = (const uint32_t*)&pA;
#pragma unroll
        for (int i = 0; i < 4; i++) sA[base + i * 4] = p[i];
        int nfr = br >> 3, nl = br & 7;
        int base2 = buf * 1024 + (nfr * 32 + nl * 4) * 2 + bo;
        const uint32_t* q = (const uint32_t*)&pB;
#pragma unroll
        for (int i = 0; i < 4; i++) sB[base2 + i * 2] = q[i];
    };
    auto comp = [&](int buf) {
        uint4 a[4]; uint2 b[4];
#pragma unroll
        for (int m = 0; m < 4; m++)
            a[m] = *(const uint4*)&sA[buf * 1024 + ((wm * 4 + m) * 32 + lane) * 4];
#pragma unroll
        for (int q = 0; q < 4; q++)
            b[q] = *(const uint2*)&sB[buf * 1024 + ((wn * 4 + q) * 32 + lane) * 2];
#pragma unroll
        for (int m = 0; m < 4; m++)
#pragma unroll
            for (int q = 0; q < 4; q++)
                mma16f(acc[m][q], (const uint32_t*)&a[m], (const uint32_t*)&b[q]);
    };

    ld(0); st(0); __syncthreads();
    for (int c = 0; c < Hdim / 16; c++) {
        int buf = c & 1;
        if (c + 1 < Hdim / 16) ld((c + 1) * 16);
        comp(buf);
        if (c + 1 < Hdim / 16) { st(buf ^ 1); __syncthreads(); }
    }

#pragma unroll
    for (int m = 0; m < 4; m++)
#pragma unroll
        for (int half = 0; half < 2; half++) {
            int row = m0 + wm * 64 + m * 16 + (lane >> 2) + half * 8;
            if (row < n) {
#pragma unroll
                for (int q = 0; q < 4; q++) {
                    int col = n0 + wn * 32 + q * 8 + (lane & 3) * 2;
                    float2 o;
                    o.x = acc[m][q][half * 2 + 0] + Bv[col];
                    o.y = acc[m][q][half * 2 + 1] + Bv[col + 1];
                    *(float2*)&XG[(size_t)row * H3 + col] = o;
                }
            }
        }
}

// =====================================================================
// GRU step (fp16): gates = h @ W_hh^T + fused epilogue.
// Block 64g x 96n (32 j x 3 gates), K-chunk 16, 8 warps (2m x 4n).
// grid (32 jtiles, 4 gtiles, 2 dirs) = 256 CTAs -> 2/SM.
// =====================================================================
__global__ void __launch_bounds__(256, 2) k_step_f16(
    const float* __restrict__ bhh_f, const float* __restrict__ bih_f,
    const float* __restrict__ bhh_b, const float* __restrict__ bih_b,
    float* __restrict__ out, int s)
{
    __shared__ uint32_t sA[1024], sB[1536];
    int dir = blockIdx.z;
    const uint32_t* W = g_w16[dir * 2 + 1];
    const float* Bh = dir ? bhh_b : bhh_f;
    const float* Bi = dir ? bih_b : bih_f;
    const float* xg = g_xg[dir];
    int par = s & 1;
    const float*    hin  = g_h[dir][par];
    float*          hout = g_h[dir][par ^ 1];
    const uint32_t* h16  = g_h16[dir][par];
    uint32_t*       ho16 = g_h16[dir][par ^ 1];
    int tstep = dir ? (Ldim - 1 - s) : s;

    int j0 = blockIdx.x * 32;
    int g0 = blockIdx.y * 64;
    int tid = threadIdx.x, lane = tid & 31, wid = tid >> 5;
    int wm = wid >> 2, wn = wid & 3;

    bool hasA = tid < 128;
    int arow = tid >> 1, ao = tid & 1;
    bool hasB = tid < 192;
    int brow = tid >> 1, bo = tid & 1;
    int wrowB = 0;
    if (hasB) {
        int gate = brow >> 5, jl = brow & 31;
        wrowB = gate * Hdim + j0 + jl;
    }

    float acc[2][3][4];
#pragma unroll
    for (int m = 0; m < 2; m++)
#pragma unroll
        for (int gt = 0; gt < 3; gt++)
#pragma unroll
            for (int e = 0; e < 4; e++) acc[m][gt][e] = 0.f;

    uint4 pA, pB;

    auto ld = [&](int k0) {
        if (hasA)
            pA = *(const uint4*)&h16[(g0 + arow) * (Hdim / 2) + (k0 + ao * 8) / 2];
        if (hasB)
            pB = *(const uint4*)&W[(size_t)wrowB * (Hdim / 2) + (k0 + bo * 8) / 2];
    };
    auto st = [&](int buf) {
        if (hasA) {
            int mfr = arow >> 4, rh = (arow >> 3) & 1, reg = ao * 2 + rh;
            int base = buf * 512 + (mfr * 32 + (arow & 7) * 4) * 4 + reg;
            const uint32_t* p = (const uint32_t*)&pA;
#pragma unroll
            for (int i = 0; i < 4; i++) sA[base + i * 4] = p[i];
        }
        if (hasB) {
            int nfr = brow >> 3, nl = brow & 7;
            int base = buf * 768 + (nfr * 32 + nl * 4) * 2 + bo;
            const uint32_t* q = (const uint32_t*)&pB;
#pragma unroll
            for (int i = 0; i < 4; i++) sB[base + i * 2] = q[i];
        }
    };
    auto comp = [&](int buf) {
        uint4 a[2]; uint2 b[3];
#pragma unroll
        for (int m = 0; m < 2; m++)
            a[m] = *(const uint4*)&sA[buf * 512 + ((wm * 2 + m) * 32 + lane) * 4];
#pragma unroll
        for (int gt = 0; gt < 3; gt++)
            b[gt] = *(const uint2*)&sB[buf * 768 + ((gt * 4 + wn) * 32 + lane) * 2];
#pragma unroll
        for (int m = 0; m < 2; m++)
#pragma unroll
            for (int gt = 0; gt < 3; gt++)
                mma16f(acc[m][gt], (const uint32_t*)&a[m], (const uint32_t*)&b[gt]);
    };

    ld(0); st(0); __syncthreads();
    for (int c = 0; c < Hdim / 16; c++) {
        int buf = c & 1;
        if (c + 1 < Hdim / 16) ld((c + 1) * 16);
        comp(buf);
        if (c + 1 < Hdim / 16) { st(buf ^ 1); __syncthreads(); }
    }

    // ---- fused gate epilogue + fp16 round + scatter ----
#pragma unroll
    for (int m = 0; m < 2; m++) {
#pragma unroll
        for (int half = 0; half < 2; half++) {
            int g = g0 + (wm * 2 + m) * 16 + (lane >> 2) + half * 8;
            int stt = g_start[g];
            int cnt = g_start[g + 1] - stt;
            bool valid = (tstep < cnt);
            size_t abase = (size_t)(stt + tstep) * H3;
            int j = j0 + wn * 8 + (lane & 3) * 2;
            float hv[2];
#pragma unroll
            for (int cp = 0; cp < 2; cp++) {
                int jj = j + cp;
                float xr, xz, xn;
                if (valid) {
                    xr = xg[abase + jj];
                    xz = xg[abase + Hdim + jj];
                    xn = xg[abase + 2 * Hdim + jj];
                } else {
                    xr = Bi[jj]; xz = Bi[Hdim + jj]; xn = Bi[2 * Hdim + jj];
                }
                int e = half * 2 + cp;
                float r  = 1.f / (1.f + expf(-(xr + acc[m][0][e] + Bh[jj])));
                float z  = 1.f / (1.f + expf(-(xz + acc[m][1][e] + Bh[Hdim + jj])));
                float nn = tanhf(xn + r * (acc[m][2][e] + Bh[2 * Hdim + jj]));
                float hp = hin[g * Hdim + jj];
                hv[cp] = (1.f - z) * nn + z * hp;
                hout[g * Hdim + jj] = hv[cp];
                if (valid)
                    out[(size_t)(stt + tstep) * (2 * Hdim) + (size_t)dir * Hdim + jj] = hv[cp];
            }
            ho16[(g * Hdim + j) / 2] = pack2h(hv[0], hv[1]);
        }
    }
}

// ---------------- host launcher ----------------
extern "C" void kernel_launch(void* const* d_in, const int* in_sizes, int n_in,
                              void* d_out, int out_size)
{
    int nAtoms = in_sizes[0] / Hdim;

    const float* h_atom = (const float*)d_in[0];
    int iBatch, iBias, iWihF, iWhhF, iBihF, iBhhF, iWihB, iWhhB, iBihB, iBhhB;
    if (in_sizes[1] == nAtoms) {
        iBatch = 1; iBias = 2; iWihF = 3; iWhhF = 4; iBihF = 5; iBhhF = 6;
        iWihB = 7; iWhhB = 8; iBihB = 9; iBhhB = 10;
    } else {
        iBias = 1; iWihF = 2; iWhhF = 3; iBihF = 4; iBhhF = 5;
        iWihB = 6; iWhhB = 7; iBihB = 8; iBhhB = 9; iBatch = 10;
    }

    const int*   batch = (const int*)d_in[iBatch];
    const float* bias  = (const float*)d_in[iBias];
    const float* wihf  = (const float*)d_in[iWihF];
    const float* whhf  = (const float*)d_in[iWhhF];
    const float* bihf  = (const float*)d_in[iBihF];
    const float* bhhf  = (const float*)d_in[iBhhF];
    const float* wihb  = (const float*)d_in[iWihB];
    const float* whhb  = (const float*)d_in[iWhhB];
    const float* bihb  = (const float*)d_in[iBihB];
    const float* bhhb  = (const float*)d_in[iBhhB];
    float* out = (float*)d_out;

    k_meta<<<1, 512>>>(batch, nAtoms);

    dim3 gw(WELEM / 4 / 256, 4);
    k_round_w<<<gw, 256>>>(wihf, whhf, wihb, whhb);

    int n4 = nAtoms * Hdim / 4;
    k_message<<<(n4 + 255) / 256, 256>>>(h_atom, bias, n4);

    k_h0<<<Gdim, 256>>>(h_atom);

    dim3 gg(H3 / 128, (nAtoms + 127) / 128, 2);
    k_gemm_f16<<<gg, 256>>>(bihf, bihb, nAtoms);

    dim3 gs(Hdim / 32, Gdim / 64, 2);
    for (int s = 0; s < Ldim; s++) {
        k_step_f16<<<gs, 256>>>(bhhf, bihf, bhhb, bihb, out, s);
    }
}

// round 7
// speedup vs baseline: 3.2133x; 1.0608x over previous
#include <cuda_runtime.h>
#include <cuda_fp16.h>
#include <math.h>
#include <stdint.h>

#define Hdim 1024
#define H3   3072
#define Gdim 256
#define Ldim 128
#define NMAX 16384
#define WELEM (H3 * Hdim)

// ---------------- scratch (device globals; no allocations) ----------------
__device__ uint32_t g_msg16[NMAX * Hdim / 2];        // fp16x2 rounded message
__device__ uint32_t g_w16[4][WELEM / 2];             // fp16x2 weights: 0=ih_f 1=hh_f 2=ih_b 3=hh_b
__device__ float    g_xg[2][(size_t)NMAX * H3];
__device__ float    g_h[2][2][Gdim * Hdim];          // fp32 hidden (exact carry)
__device__ uint32_t g_h16[2][2][Gdim * Hdim / 2];    // fp16x2 rounded hidden (mma operand)
__device__ int      g_start[Gdim + 1];

// ---------------- helpers ----------------
__device__ __forceinline__ uint32_t pack2h(float x, float y) {
    __half2 h = __halves2half2(__float2half_rn(x), __float2half_rn(y));
    return *reinterpret_cast<uint32_t*>(&h);
}
__device__ __forceinline__ void mma16f(float* d, const uint32_t* a, const uint32_t* b) {
    asm volatile(
        "mma.sync.aligned.m16n8k16.row.col.f32.f16.f16.f32 "
        "{%0,%1,%2,%3}, {%4,%5,%6,%7}, {%8,%9}, {%0,%1,%2,%3};\n"
        : "+f"(d[0]), "+f"(d[1]), "+f"(d[2]), "+f"(d[3])
        : "r"(a[0]), "r"(a[1]), "r"(a[2]), "r"(a[3]), "r"(b[0]), "r"(b[1]));
}

// ---------------- meta: segment starts ----------------
__global__ void k_meta(const int* __restrict__ batch, int n) {
    int g = threadIdx.x;
    if (g > Gdim) return;
    int lo = 0, hi = n;
    while (lo < hi) {
        int mid = (lo + hi) >> 1;
        if (batch[mid] < g) lo = mid + 1; else hi = mid;
    }
    g_start[g] = lo;
}

// ---------------- weight round (fp32 -> fp16) ----------------
__global__ void k_round_w(const float* __restrict__ w0, const float* __restrict__ w1,
                          const float* __restrict__ w2, const float* __restrict__ w3) {
    int which = blockIdx.y;
    const float* src = which == 0 ? w0 : which == 1 ? w1 : which == 2 ? w2 : w3;
    int i = blockIdx.x * blockDim.x + threadIdx.x;
    if (i >= WELEM / 4) return;
    float4 v = ((const float4*)src)[i];
    ((uint2*)g_w16[which])[i] = make_uint2(pack2h(v.x, v.y), pack2h(v.z, v.w));
}

// ---------------- message = relu(h_atom + bias) -> fp16 ----------------
__global__ void k_message(const float* __restrict__ h_atom,
                          const float* __restrict__ bias, int n4) {
    int i = blockIdx.x * blockDim.x + threadIdx.x;
    if (i >= n4) return;
    float4 v = ((const float4*)h_atom)[i];
    float4 b = ((const float4*)bias)[i & (Hdim / 4 - 1)];
    v.x = fmaxf(v.x + b.x, 0.f);
    v.y = fmaxf(v.y + b.y, 0.f);
    v.z = fmaxf(v.z + b.z, 0.f);
    v.w = fmaxf(v.w + b.w, 0.f);
    ((uint2*)g_msg16)[i] = make_uint2(pack2h(v.x, v.y), pack2h(v.z, v.w));
}

// ---------------- h0 = segment max; fp32 + fp16, both dirs ----------------
__global__ void k_h0(const float* __restrict__ h_atom) {
    int g = blockIdx.x;
    int c = threadIdx.x * 4;
    int s0 = g_start[g], s1 = g_start[g + 1];
    float4 m = make_float4(-3.4e38f, -3.4e38f, -3.4e38f, -3.4e38f);
    for (int r = s0; r < s1; r++) {
        float4 v = *(const float4*)&h_atom[(size_t)r * Hdim + c];
        m.x = fmaxf(m.x, v.x); m.y = fmaxf(m.y, v.y);
        m.z = fmaxf(m.z, v.z); m.w = fmaxf(m.w, v.w);
    }
    if (s1 == s0) m = make_float4(0.f, 0.f, 0.f, 0.f);
    int fi = g * Hdim + c;
    uint2 p = make_uint2(pack2h(m.x, m.y), pack2h(m.z, m.w));
#pragma unroll
    for (int d = 0; d < 2; d++) {
        *(float4*)&g_h[d][0][fi] = m;
        ((uint2*)g_h16[d][0])[fi / 4] = p;
    }
}

// =====================================================================
// Input GEMM (fp16): XG[n x 3072] = msg @ W_ih^T + b_ih
// Block 128m x 128n, K-chunk 16, 8 warps (2m x 4n), warp 64x32.
// =====================================================================
__global__ void __launch_bounds__(256) k_gemm_f16(
    const float* __restrict__ bi_f, const float* __restrict__ bi_b, int n)
{
    __shared__ uint32_t sA[2048], sB[2048];
    int dir = blockIdx.z;
    const uint32_t* W = g_w16[dir * 2];
    const float* Bv = dir ? bi_b : bi_f;
    float* XG = g_xg[dir];
    int n0 = blockIdx.x * 128;
    int m0 = blockIdx.y * 128;
    int tid = threadIdx.x, lane = tid & 31, wid = tid >> 5;
    int wm = wid >> 2, wn = wid & 3;

    int ar = tid >> 1, ao = tid & 1;
    int br = tid >> 1, bo = tid & 1;

    float acc[4][4][4];
#pragma unroll
    for (int m = 0; m < 4; m++)
#pragma unroll
        for (int q = 0; q < 4; q++)
#pragma unroll
            for (int e = 0; e < 4; e++) acc[m][q][e] = 0.f;

    uint4 pA, pB;

    auto ld = [&](int k0) {
        int rg = m0 + ar;
        if (rg < n) pA = *(const uint4*)&g_msg16[rg * (Hdim / 2) + (k0 + ao * 8) / 2];
        else        pA = make_uint4(0, 0, 0, 0);
        pB = *(const uint4*)&W[(size_t)(n0 + br) * (Hdim / 2) + (k0 + bo * 8) / 2];
    };
    auto st = [&](int buf) {
        int mfr = ar >> 4, rh = (ar >> 3) & 1, reg = ao * 2 + rh;
        int base = buf * 1024 + (mfr * 32 + (ar & 7) * 4) * 4 + reg;
        const uint32_t* p = (const uint32_t*)&pA;
#pragma unroll
        for (int i = 0; i < 4; i++) sA[base + i * 4] = p[i];
        int nfr = br >> 3, nl = br & 7;
        int base2 = buf * 1024 + (nfr * 32 + nl * 4) * 2 + bo;
        const uint32_t* q = (const uint32_t*)&pB;
#pragma unroll
        for (int i = 0; i < 4; i++) sB[base2 + i * 2] = q[i];
    };
    auto comp = [&](int buf) {
        uint4 a[4]; uint2 b[4];
#pragma unroll
        for (int m = 0; m < 4; m++)
            a[m] = *(const uint4*)&sA[buf * 1024 + ((wm * 4 + m) * 32 + lane) * 4];
#pragma unroll
        for (int q = 0; q < 4; q++)
            b[q] = *(const uint2*)&sB[buf * 1024 + ((wn * 4 + q) * 32 + lane) * 2];
#pragma unroll
        for (int m = 0; m < 4; m++)
#pragma unroll
            for (int q = 0; q < 4; q++)
                mma16f(acc[m][q], (const uint32_t*)&a[m], (const uint32_t*)&b[q]);
    };

    ld(0); st(0); __syncthreads();
    for (int c = 0; c < Hdim / 16; c++) {
        int buf = c & 1;
        if (c + 1 < Hdim / 16) ld((c + 1) * 16);
        comp(buf);
        if (c + 1 < Hdim / 16) { st(buf ^ 1); __syncthreads(); }
    }

#pragma unroll
    for (int m = 0; m < 4; m++)
#pragma unroll
        for (int half = 0; half < 2; half++) {
            int row = m0 + wm * 64 + m * 16 + (lane >> 2) + half * 8;
            if (row < n) {
#pragma unroll
                for (int q = 0; q < 4; q++) {
                    int col = n0 + wn * 32 + q * 8 + (lane & 3) * 2;
                    float2 o;
                    o.x = acc[m][q][half * 2 + 0] + Bv[col];
                    o.y = acc[m][q][half * 2 + 1] + Bv[col + 1];
                    *(float2*)&XG[(size_t)row * H3 + col] = o;
                }
            }
        }
}

// =====================================================================
// GRU step (fp16): gates = h @ W_hh^T + fused epilogue.
// Block 64g x 96n (32 j x 3 gates), K-chunk 32, 32 iters,
// 3 smem buffers + 2-deep register prefetch. 8 warps (2m x 4n).
// grid (32 jtiles, 4 gtiles, 2 dirs) = 256 CTAs -> 2/SM.
// =====================================================================
#define NCH 32   // 1024 / 32

__global__ void __launch_bounds__(256, 2) k_step_f16(
    const float* __restrict__ bhh_f, const float* __restrict__ bih_f,
    const float* __restrict__ bhh_b, const float* __restrict__ bih_b,
    float* __restrict__ out, int s)
{
    __shared__ uint32_t sA[3 * 1024], sB[3 * 1536];
    int dir = blockIdx.z;
    const uint32_t* W = g_w16[dir * 2 + 1];
    const float* Bh = dir ? bhh_b : bhh_f;
    const float* Bi = dir ? bih_b : bih_f;
    const float* xg = g_xg[dir];
    int par = s & 1;
    const float*    hin  = g_h[dir][par];
    float*          hout = g_h[dir][par ^ 1];
    const uint32_t* h16  = g_h16[dir][par];
    uint32_t*       ho16 = g_h16[dir][par ^ 1];
    int tstep = dir ? (Ldim - 1 - s) : s;

    int j0 = blockIdx.x * 32;
    int g0 = blockIdx.y * 64;
    int tid = threadIdx.x, lane = tid & 31, wid = tid >> 5;
    int wm = wid >> 2, wn = wid & 3;

    // A loader: all 256 threads, one uint4 (octet) each: row ar, k-octet aoct
    int ar = tid >> 2, aoct = tid & 3;
    // B loader: tid < 192, two uint4 each: row br, k16-half bk (octets 2bk, 2bk+1)
    bool hasB = tid < 192;
    int br = tid >> 1, bk = tid & 1;
    int wrowB = (br >> 5) * Hdim + j0 + (br & 31);

    float acc[2][3][4];
#pragma unroll
    for (int m = 0; m < 2; m++)
#pragma unroll
        for (int gt = 0; gt < 3; gt++)
#pragma unroll
            for (int e = 0; e < 4; e++) acc[m][gt][e] = 0.f;

    uint4 rA[2], rB0[2], rB1[2];

    auto ld = [&](int c, int rs) {
        rA[rs] = *(const uint4*)&h16[(g0 + ar) * (Hdim / 2) + c * 16 + aoct * 4];
        if (hasB) {
            const uint32_t* wp = &W[(size_t)wrowB * (Hdim / 2) + c * 16 + bk * 8];
            rB0[rs] = *(const uint4*)wp;
            rB1[rs] = *(const uint4*)(wp + 4);
        }
    };
    auto st = [&](int buf, int rs) {
        {
            int kf = aoct >> 1, oo = aoct & 1;
            int mfr = ar >> 4, rr = ar & 15;
            int reg = oo * 2 + (rr >> 3);
            int base = buf * 1024 + ((kf * 4 + mfr) * 32 + (rr & 7) * 4) * 4 + reg;
            const uint32_t* p = (const uint32_t*)&rA[rs];
#pragma unroll
            for (int e = 0; e < 4; e++) sA[base + e * 4] = p[e];
        }
        if (hasB) {
            int nfr = br >> 3, nl = br & 7;
            int base = buf * 1536 + ((bk * 12 + nfr) * 32 + nl * 4) * 2;
            const uint32_t* p0 = (const uint32_t*)&rB0[rs];
            const uint32_t* p1 = (const uint32_t*)&rB1[rs];
#pragma unroll
            for (int e = 0; e < 4; e++) {
                sB[base + e * 2 + 0] = p0[e];
                sB[base + e * 2 + 1] = p1[e];
            }
        }
    };
    auto comp = [&](int buf) {
#pragma unroll
        for (int kf = 0; kf < 2; kf++) {
            uint4 a[2]; uint2 b[3];
#pragma unroll
            for (int m = 0; m < 2; m++)
                a[m] = *(const uint4*)&sA[buf * 1024 + ((kf * 4 + wm * 2 + m) * 32 + lane) * 4];
#pragma unroll
            for (int gt = 0; gt < 3; gt++)
                b[gt] = *(const uint2*)&sB[buf * 1536 + ((kf * 12 + gt * 4 + wn) * 32 + lane) * 2];
#pragma unroll
            for (int m = 0; m < 2; m++)
#pragma unroll
                for (int gt = 0; gt < 3; gt++)
                    mma16f(acc[m][gt], (const uint32_t*)&a[m], (const uint32_t*)&b[gt]);
        }
    };

    // prologue: chunk0 -> buf0, chunk1 in regs
    ld(0, 0); st(0, 0); ld(1, 1);
    __syncthreads();
#pragma unroll 6
    for (int c = 0; c < NCH; c++) {
        int buf = c % 3;
        if (c + 2 < NCH) ld(c + 2, c & 1);
        comp(buf);
        if (c + 1 < NCH) {
            st((c + 1) % 3, (c + 1) & 1);
            __syncthreads();
        }
    }

    // ---- fused gate epilogue + fp16 round + scatter ----
#pragma unroll
    for (int m = 0; m < 2; m++) {
#pragma unroll
        for (int half = 0; half < 2; half++) {
            int g = g0 + (wm * 2 + m) * 16 + (lane >> 2) + half * 8;
            int stt = g_start[g];
            int cnt = g_start[g + 1] - stt;
            bool valid = (tstep < cnt);
            size_t abase = (size_t)(stt + tstep) * H3;
            int j = j0 + wn * 8 + (lane & 3) * 2;
            float hv[2];
#pragma unroll
            for (int cp = 0; cp < 2; cp++) {
                int jj = j + cp;
                float xr, xz, xn;
                if (valid) {
                    xr = xg[abase + jj];
                    xz = xg[abase + Hdim + jj];
                    xn = xg[abase + 2 * Hdim + jj];
                } else {
                    xr = Bi[jj]; xz = Bi[Hdim + jj]; xn = Bi[2 * Hdim + jj];
                }
                int e = half * 2 + cp;
                float r  = 1.f / (1.f + expf(-(xr + acc[m][0][e] + Bh[jj])));
                float z  = 1.f / (1.f + expf(-(xz + acc[m][1][e] + Bh[Hdim + jj])));
                float nn = tanhf(xn + r * (acc[m][2][e] + Bh[2 * Hdim + jj]));
                float hp = hin[g * Hdim + jj];
                hv[cp] = (1.f - z) * nn + z * hp;
                hout[g * Hdim + jj] = hv[cp];
                if (valid)
                    out[(size_t)(stt + tstep) * (2 * Hdim) + (size_t)dir * Hdim + jj] = hv[cp];
            }
            ho16[(g * Hdim + j) / 2] = pack2h(hv[0], hv[1]);
        }
    }
}

// ---------------- host launcher ----------------
extern "C" void kernel_launch(void* const* d_in, const int* in_sizes, int n_in,
                              void* d_out, int out_size)
{
    int nAtoms = in_sizes[0] / Hdim;

    const float* h_atom = (const float*)d_in[0];
    int iBatch, iBias, iWihF, iWhhF, iBihF, iBhhF, iWihB, iWhhB, iBihB, iBhhB;
    if (in_sizes[1] == nAtoms) {
        iBatch = 1; iBias = 2; iWihF = 3; iWhhF = 4; iBihF = 5; iBhhF = 6;
        iWihB = 7; iWhhB = 8; iBihB = 9; iBhhB = 10;
    } else {
        iBias = 1; iWihF = 2; iWhhF = 3; iBihF = 4; iBhhF = 5;
        iWihB = 6; iWhhB = 7; iBihB = 8; iBhhB = 9; iBatch = 10;
    }

    const int*   batch = (const int*)d_in[iBatch];
    const float* bias  = (const float*)d_in[iBias];
    const float* wihf  = (const float*)d_in[iWihF];
    const float* whhf  = (const float*)d_in[iWhhF];
    const float* bihf  = (const float*)d_in[iBihF];
    const float* bhhf  = (const float*)d_in[iBhhF];
    const float* wihb  = (const float*)d_in[iWihB];
    const float* whhb  = (const float*)d_in[iWhhB];
    const float* bihb  = (const float*)d_in[iBihB];
    const float* bhhb  = (const float*)d_in[iBhhB];
    float* out = (float*)d_out;

    k_meta<<<1, 512>>>(batch, nAtoms);

    dim3 gw(WELEM / 4 / 256, 4);
    k_round_w<<<gw, 256>>>(wihf, whhf, wihb, whhb);

    int n4 = nAtoms * Hdim / 4;
    k_message<<<(n4 + 255) / 256, 256>>>(h_atom, bias, n4);

    k_h0<<<Gdim, 256>>>(h_atom);

    dim3 gg(H3 / 128, (nAtoms + 127) / 128, 2);
    k_gemm_f16<<<gg, 256>>>(bihf, bihb, nAtoms);

    dim3 gs(Hdim / 32, Gdim / 64, 2);
    for (int s = 0; s < Ldim; s++) {
        k_step_f16<<<gs, 256>>>(bhhf, bihf, bhhb, bihb, out, s);
    }
}

// round 8
// speedup vs baseline: 3.2150x; 1.0005x over previous
#include <cuda_runtime.h>
#include <cuda_fp16.h>
#include <math.h>
#include <stdint.h>

#define Hdim 1024
#define H3   3072
#define Gdim 256
#define Ldim 128
#define NMAX 16384
#define WELEM (H3 * Hdim)

// ---------------- scratch (device globals; no allocations) ----------------
__device__ uint32_t g_msg16[NMAX * Hdim / 2];        // fp16x2 rounded message
__device__ uint32_t g_w16[4][WELEM / 2];             // fp16x2 weights: 0=ih_f 1=hh_f 2=ih_b 3=hh_b
__device__ float    g_xg[2][(size_t)NMAX * H3];
__device__ float    g_h[2][2][Gdim * Hdim];          // fp32 hidden (exact carry)
__device__ uint32_t g_h16[2][2][Gdim * Hdim / 2];    // fp16x2 rounded hidden (mma operand)
__device__ int      g_start[Gdim + 1];

// ---------------- helpers ----------------
__device__ __forceinline__ uint32_t pack2h(float x, float y) {
    __half2 h = __halves2half2(__float2half_rn(x), __float2half_rn(y));
    return *reinterpret_cast<uint32_t*>(&h);
}
__device__ __forceinline__ void mma16f(float* d, const uint32_t* a, const uint32_t* b) {
    asm volatile(
        "mma.sync.aligned.m16n8k16.row.col.f32.f16.f16.f32 "
        "{%0,%1,%2,%3}, {%4,%5,%6,%7}, {%8,%9}, {%0,%1,%2,%3};\n"
        : "+f"(d[0]), "+f"(d[1]), "+f"(d[2]), "+f"(d[3])
        : "r"(a[0]), "r"(a[1]), "r"(a[2]), "r"(a[3]), "r"(b[0]), "r"(b[1]));
}

// ---------------- meta: segment starts ----------------
__global__ void k_meta(const int* __restrict__ batch, int n) {
    int g = threadIdx.x;
    if (g > Gdim) return;
    int lo = 0, hi = n;
    while (lo < hi) {
        int mid = (lo + hi) >> 1;
        if (batch[mid] < g) lo = mid + 1; else hi = mid;
    }
    g_start[g] = lo;
}

// ---------------- weight round (fp32 -> fp16) ----------------
__global__ void k_round_w(const float* __restrict__ w0, const float* __restrict__ w1,
                          const float* __restrict__ w2, const float* __restrict__ w3) {
    int which = blockIdx.y;
    const float* src = which == 0 ? w0 : which == 1 ? w1 : which == 2 ? w2 : w3;
    int i = blockIdx.x * blockDim.x + threadIdx.x;
    if (i >= WELEM / 4) return;
    float4 v = ((const float4*)src)[i];
    ((uint2*)g_w16[which])[i] = make_uint2(pack2h(v.x, v.y), pack2h(v.z, v.w));
}

// ---------------- message = relu(h_atom + bias) -> fp16 ----------------
__global__ void k_message(const float* __restrict__ h_atom,
                          const float* __restrict__ bias, int n4) {
    int i = blockIdx.x * blockDim.x + threadIdx.x;
    if (i >= n4) return;
    float4 v = ((const float4*)h_atom)[i];
    float4 b = ((const float4*)bias)[i & (Hdim / 4 - 1)];
    v.x = fmaxf(v.x + b.x, 0.f);
    v.y = fmaxf(v.y + b.y, 0.f);
    v.z = fmaxf(v.z + b.z, 0.f);
    v.w = fmaxf(v.w + b.w, 0.f);
    ((uint2*)g_msg16)[i] = make_uint2(pack2h(v.x, v.y), pack2h(v.z, v.w));
}

// ---------------- h0 = segment max; fp32 + fp16, both dirs ----------------
__global__ void k_h0(const float* __restrict__ h_atom) {
    int g = blockIdx.x;
    int c = threadIdx.x * 4;
    int s0 = g_start[g], s1 = g_start[g + 1];
    float4 m = make_float4(-3.4e38f, -3.4e38f, -3.4e38f, -3.4e38f);
    for (int r = s0; r < s1; r++) {
        float4 v = *(const float4*)&h_atom[(size_t)r * Hdim + c];
        m.x = fmaxf(m.x, v.x); m.y = fmaxf(m.y, v.y);
        m.z = fmaxf(m.z, v.z); m.w = fmaxf(m.w, v.w);
    }
    if (s1 == s0) m = make_float4(0.f, 0.f, 0.f, 0.f);
    int fi = g * Hdim + c;
    uint2 p = make_uint2(pack2h(m.x, m.y), pack2h(m.z, m.w));
#pragma unroll
    for (int d = 0; d < 2; d++) {
        *(float4*)&g_h[d][0][fi] = m;
        ((uint2*)g_h16[d][0])[fi / 4] = p;
    }
}

// =====================================================================
// Input GEMM (fp16): XG[n x 3072] = msg @ W_ih^T + b_ih
// Block 128m x 128n, K-chunk 16, 8 warps (2m x 4n), warp 64x32.
// =====================================================================
__global__ void __launch_bounds__(256) k_gemm_f16(
    const float* __restrict__ bi_f, const float* __restrict__ bi_b, int n)
{
    __shared__ uint32_t sA[2048], sB[2048];
    int dir = blockIdx.z;
    const uint32_t* W = g_w16[dir * 2];
    const float* Bv = dir ? bi_b : bi_f;
    float* XG = g_xg[dir];
    int n0 = blockIdx.x * 128;
    int m0 = blockIdx.y * 128;
    int tid = threadIdx.x, lane = tid & 31, wid = tid >> 5;
    int wm = wid >> 2, wn = wid & 3;

    int ar = tid >> 1, ao = tid & 1;
    int br = tid >> 1, bo = tid & 1;

    float acc[4][4][4];
#pragma unroll
    for (int m = 0; m < 4; m++)
#pragma unroll
        for (int q = 0; q < 4; q++)
#pragma unroll
            for (int e = 0; e < 4; e++) acc[m][q][e] = 0.f;

    uint4 pA, pB;

    auto ld = [&](int k0) {
        int rg = m0 + ar;
        if (rg < n) pA = *(const uint4*)&g_msg16[rg * (Hdim / 2) + (k0 + ao * 8) / 2];
        else        pA = make_uint4(0, 0, 0, 0);
        pB = *(const uint4*)&W[(size_t)(n0 + br) * (Hdim / 2) + (k0 + bo * 8) / 2];
    };
    auto st = [&](int buf) {
        int mfr = ar >> 4, rh = (ar >> 3) & 1, reg = ao * 2 + rh;
        int base = buf * 1024 + (mfr * 32 + (ar & 7) * 4) * 4 + reg;
        const uint32_t* p = (const uint32_t*)&pA;
#pragma unroll
        for (int i = 0; i < 4; i++) sA[base + i * 4] = p[i];
        int nfr = br >> 3, nl = br & 7;
        int base2 = buf * 1024 + (nfr * 32 + nl * 4) * 2 + bo;
        const uint32_t* q = (const uint32_t*)&pB;
#pragma unroll
        for (int i = 0; i < 4; i++) sB[base2 + i * 2] = q[i];
    };
    auto comp = [&](int buf) {
        uint4 a[4]; uint2 b[4];
#pragma unroll
        for (int m = 0; m < 4; m++)
            a[m] = *(const uint4*)&sA[buf * 1024 + ((wm * 4 + m) * 32 + lane) * 4];
#pragma unroll
        for (int q = 0; q < 4; q++)
            b[q] = *(const uint2*)&sB[buf * 1024 + ((wn * 4 + q) * 32 + lane) * 2];
#pragma unroll
        for (int m = 0; m < 4; m++)
#pragma unroll
            for (int q = 0; q < 4; q++)
                mma16f(acc[m][q], (const uint32_t*)&a[m], (const uint32_t*)&b[q]);
    };

    ld(0); st(0); __syncthreads();
    for (int c = 0; c < Hdim / 16; c++) {
        int buf = c & 1;
        if (c + 1 < Hdim / 16) ld((c + 1) * 16);
        comp(buf);
        if (c + 1 < Hdim / 16) { st(buf ^ 1); __syncthreads(); }
    }

#pragma unroll
    for (int m = 0; m < 4; m++)
#pragma unroll
        for (int half = 0; half < 2; half++) {
            int row = m0 + wm * 64 + m * 16 + (lane >> 2) + half * 8;
            if (row < n) {
#pragma unroll
                for (int q = 0; q < 4; q++) {
                    int col = n0 + wn * 32 + q * 8 + (lane & 3) * 2;
                    float2 o;
                    o.x = acc[m][q][half * 2 + 0] + Bv[col];
                    o.y = acc[m][q][half * 2 + 1] + Bv[col + 1];
                    *(float2*)&XG[(size_t)row * H3 + col] = o;
                }
            }
        }
}

// =====================================================================
// GRU step (fp16): gates = h @ W_hh^T + fused epilogue.
// Block 64g x 96n (32 j x 3 gates), K-chunk 32, 32 iters,
// 3 smem buffers + 2-deep register prefetch. 8 warps (2m x 4n).
// grid (32 jtiles, 4 gtiles, 2 dirs) = 256 CTAs -> 2/SM.
// =====================================================================
#define NCH 32   // 1024 / 32

__global__ void __launch_bounds__(256, 2) k_step_f16(
    const float* __restrict__ bhh_f, const float* __restrict__ bih_f,
    const float* __restrict__ bhh_b, const float* __restrict__ bih_b,
    float* __restrict__ out, int s)
{
    __shared__ uint32_t sA[3 * 1024], sB[3 * 1536];
    int dir = blockIdx.z;
    const uint32_t* W = g_w16[dir * 2 + 1];
    const float* Bh = dir ? bhh_b : bhh_f;
    const float* Bi = dir ? bih_b : bih_f;
    const float* xg = g_xg[dir];
    int par = s & 1;
    const float*    hin  = g_h[dir][par];
    float*          hout = g_h[dir][par ^ 1];
    const uint32_t* h16  = g_h16[dir][par];
    uint32_t*       ho16 = g_h16[dir][par ^ 1];
    int tstep = dir ? (Ldim - 1 - s) : s;

    int j0 = blockIdx.x * 32;
    int g0 = blockIdx.y * 64;
    int tid = threadIdx.x, lane = tid & 31, wid = tid >> 5;
    int wm = wid >> 2, wn = wid & 3;

    // A loader: all 256 threads, one uint4 (octet) each: row ar, k-octet aoct
    int ar = tid >> 2, aoct = tid & 3;
    // B loader: tid < 192, two uint4 each: row br, k16-half bk (octets 2bk, 2bk+1)
    bool hasB = tid < 192;
    int br = tid >> 1, bk = tid & 1;
    int wrowB = (br >> 5) * Hdim + j0 + (br & 31);

    float acc[2][3][4];
#pragma unroll
    for (int m = 0; m < 2; m++)
#pragma unroll
        for (int gt = 0; gt < 3; gt++)
#pragma unroll
            for (int e = 0; e < 4; e++) acc[m][gt][e] = 0.f;

    uint4 rA[2], rB0[2], rB1[2];

    auto ld = [&](int c, int rs) {
        rA[rs] = *(const uint4*)&h16[(g0 + ar) * (Hdim / 2) + c * 16 + aoct * 4];
        if (hasB) {
            const uint32_t* wp = &W[(size_t)wrowB * (Hdim / 2) + c * 16 + bk * 8];
            rB0[rs] = *(const uint4*)wp;
            rB1[rs] = *(const uint4*)(wp + 4);
        }
    };
    auto st = [&](int buf, int rs) {
        {
            int kf = aoct >> 1, oo = aoct & 1;
            int mfr = ar >> 4, rr = ar & 15;
            int reg = oo * 2 + (rr >> 3);
            int base = buf * 1024 + ((kf * 4 + mfr) * 32 + (rr & 7) * 4) * 4 + reg;
            const uint32_t* p = (const uint32_t*)&rA[rs];
#pragma unroll
            for (int e = 0; e < 4; e++) sA[base + e * 4] = p[e];
        }
        if (hasB) {
            int nfr = br >> 3, nl = br & 7;
            int base = buf * 1536 + ((bk * 12 + nfr) * 32 + nl * 4) * 2;
            const uint32_t* p0 = (const uint32_t*)&rB0[rs];
            const uint32_t* p1 = (const uint32_t*)&rB1[rs];
#pragma unroll
            for (int e = 0; e < 4; e++) {
                sB[base + e * 2 + 0] = p0[e];
                sB[base + e * 2 + 1] = p1[e];
            }
        }
    };
    auto comp = [&](int buf) {
#pragma unroll
        for (int kf = 0; kf < 2; kf++) {
            uint4 a[2]; uint2 b[3];
#pragma unroll
            for (int m = 0; m < 2; m++)
                a[m] = *(const uint4*)&sA[buf * 1024 + ((kf * 4 + wm * 2 + m) * 32 + lane) * 4];
#pragma unroll
            for (int gt = 0; gt < 3; gt++)
                b[gt] = *(const uint2*)&sB[buf * 1536 + ((kf * 12 + gt * 4 + wn) * 32 + lane) * 2];
#pragma unroll
            for (int m = 0; m < 2; m++)
#pragma unroll
                for (int gt = 0; gt < 3; gt++)
                    mma16f(acc[m][gt], (const uint32_t*)&a[m], (const uint32_t*)&b[gt]);
        }
    };

    // prologue: chunk0 -> buf0, chunk1 in regs
    ld(0, 0); st(0, 0); ld(1, 1);
    __syncthreads();
#pragma unroll 6
    for (int c = 0; c < NCH; c++) {
        int buf = c % 3;
        if (c + 2 < NCH) ld(c + 2, c & 1);
        comp(buf);
        if (c + 1 < NCH) {
            st((c + 1) % 3, (c + 1) & 1);
            __syncthreads();
        }
    }

    // ---- fused gate epilogue + fp16 round + scatter ----
#pragma unroll
    for (int m = 0; m < 2; m++) {
#pragma unroll
        for (int half = 0; half < 2; half++) {
            int g = g0 + (wm * 2 + m) * 16 + (lane >> 2) + half * 8;
            int stt = g_start[g];
            int cnt = g_start[g + 1] - stt;
            bool valid = (tstep < cnt);
            size_t abase = (size_t)(stt + tstep) * H3;
            int j = j0 + wn * 8 + (lane & 3) * 2;
            float hv[2];
#pragma unroll
            for (int cp = 0; cp < 2; cp++) {
                int jj = j + cp;
                float xr, xz, xn;
                if (valid) {
                    xr = xg[abase + jj];
                    xz = xg[abase + Hdim + jj];
                    xn = xg[abase + 2 * Hdim + jj];
                } else {
                    xr = Bi[jj]; xz = Bi[Hdim + jj]; xn = Bi[2 * Hdim + jj];
                }
                int e = half * 2 + cp;
                float r  = 1.f / (1.f + expf(-(xr + acc[m][0][e] + Bh[jj])));
                float z  = 1.f / (1.f + expf(-(xz + acc[m][1][e] + Bh[Hdim + jj])));
                float nn = tanhf(xn + r * (acc[m][2][e] + Bh[2 * Hdim + jj]));
                float hp = hin[g * Hdim + jj];
                hv[cp] = (1.f - z) * nn + z * hp;
                hout[g * Hdim + jj] = hv[cp];
                if (valid)
                    out[(size_t)(stt + tstep) * (2 * Hdim) + (size_t)dir * Hdim + jj] = hv[cp];
            }
            ho16[(g * Hdim + j) / 2] = pack2h(hv[0], hv[1]);
        }
    }
}

// ---------------- host launcher ----------------
extern "C" void kernel_launch(void* const* d_in, const int* in_sizes, int n_in,
                              void* d_out, int out_size)
{
    int nAtoms = in_sizes[0] / Hdim;

    const float* h_atom = (const float*)d_in[0];
    int iBatch, iBias, iWihF, iWhhF, iBihF, iBhhF, iWihB, iWhhB, iBihB, iBhhB;
    if (in_sizes[1] == nAtoms) {
        iBatch = 1; iBias = 2; iWihF = 3; iWhhF = 4; iBihF = 5; iBhhF = 6;
        iWihB = 7; iWhhB = 8; iBihB = 9; iBhhB = 10;
    } else {
        iBias = 1; iWihF = 2; iWhhF = 3; iBihF = 4; iBhhF = 5;
        iWihB = 6; iWhhB = 7; iBihB = 8; iBhhB = 9; iBatch = 10;
    }

    const int*   batch = (const int*)d_in[iBatch];
    const float* bias  = (const float*)d_in[iBias];
    const float* wihf  = (const float*)d_in[iWihF];
    const float* whhf  = (const float*)d_in[iWhhF];
    const float* bihf  = (const float*)d_in[iBihF];
    const float* bhhf  = (const float*)d_in[iBhhF];
    const float* wihb  = (const float*)d_in[iWihB];
    const float* whhb  = (const float*)d_in[iWhhB];
    const float* bihb  = (const float*)d_in[iBihB];
    const float* bhhb  = (const float*)d_in[iBhhB];
    float* out = (float*)d_out;

    k_meta<<<1, 512>>>(batch, nAtoms);

    dim3 gw(WELEM / 4 / 256, 4);
    k_round_w<<<gw, 256>>>(wihf, whhf, wihb, whhb);

    int n4 = nAtoms * Hdim / 4;
    k_message<<<(n4 + 255) / 256, 256>>>(h_atom, bias, n4);

    k_h0<<<Gdim, 256>>>(h_atom);

    dim3 gg(H3 / 128, (nAtoms + 127) / 128, 2);
    k_gemm_f16<<<gg, 256>>>(bihf, bihb, nAtoms);

    dim3 gs(Hdim / 32, Gdim / 64, 2);
    for (int s = 0; s < Ldim; s++) {
        k_step_f16<<<gs, 256>>>(bhhf, bihf, bhhb, bihb, out, s);
    }
}

// round 9
// speedup vs baseline: 3.2174x; 1.0008x over previous
#include <cuda_runtime.h>
#include <cuda_fp16.h>
#include <math.h>
#include <stdint.h>

#define Hdim 1024
#define H3   3072
#define Gdim 256
#define Ldim 128
#define NMAX 16384
#define WELEM (H3 * Hdim)

// ---------------- scratch (device globals; no allocations) ----------------
__device__ uint32_t g_msg16[NMAX * Hdim / 2];        // fp16x2 rounded message
__device__ uint32_t g_w16[4][WELEM / 2];             // fp16x2 weights: 0=ih_f 1=hh_f 2=ih_b 3=hh_b
__device__ float    g_xg[2][(size_t)NMAX * H3];
__device__ float    g_h[2][2][Gdim * Hdim];          // fp32 hidden (exact carry)
__device__ uint32_t g_h16[2][2][Gdim * Hdim / 2];    // fp16x2 rounded hidden (mma operand)
__device__ int      g_start[Gdim + 1];

// ---------------- helpers ----------------
__device__ __forceinline__ uint32_t pack2h(float x, float y) {
    __half2 h = __halves2half2(__float2half_rn(x), __float2half_rn(y));
    return *reinterpret_cast<uint32_t*>(&h);
}
__device__ __forceinline__ void mma16f(float* d, const uint32_t* a, const uint32_t* b) {
    asm volatile(
        "mma.sync.aligned.m16n8k16.row.col.f32.f16.f16.f32 "
        "{%0,%1,%2,%3}, {%4,%5,%6,%7}, {%8,%9}, {%0,%1,%2,%3};\n"
        : "+f"(d[0]), "+f"(d[1]), "+f"(d[2]), "+f"(d[3])
        : "r"(a[0]), "r"(a[1]), "r"(a[2]), "r"(a[3]), "r"(b[0]), "r"(b[1]));
}

// ---------------- meta: segment starts ----------------
__global__ void k_meta(const int* __restrict__ batch, int n) {
    int g = threadIdx.x;
    if (g > Gdim) return;
    int lo = 0, hi = n;
    while (lo < hi) {
        int mid = (lo + hi) >> 1;
        if (batch[mid] < g) lo = mid + 1; else hi = mid;
    }
    g_start[g] = lo;
}

// ---------------- weight round (fp32 -> fp16) ----------------
__global__ void k_round_w(const float* __restrict__ w0, const float* __restrict__ w1,
                          const float* __restrict__ w2, const float* __restrict__ w3) {
    int which = blockIdx.y;
    const float* src = which == 0 ? w0 : which == 1 ? w1 : which == 2 ? w2 : w3;
    int i = blockIdx.x * blockDim.x + threadIdx.x;
    if (i >= WELEM / 4) return;
    float4 v = ((const float4*)src)[i];
    ((uint2*)g_w16[which])[i] = make_uint2(pack2h(v.x, v.y), pack2h(v.z, v.w));
}

// ---------------- message = relu(h_atom + bias) -> fp16 ----------------
__global__ void k_message(const float* __restrict__ h_atom,
                          const float* __restrict__ bias, int n4) {
    int i = blockIdx.x * blockDim.x + threadIdx.x;
    if (i >= n4) return;
    float4 v = ((const float4*)h_atom)[i];
    float4 b = ((const float4*)bias)[i & (Hdim / 4 - 1)];
    v.x = fmaxf(v.x + b.x, 0.f);
    v.y = fmaxf(v.y + b.y, 0.f);
    v.z = fmaxf(v.z + b.z, 0.f);
    v.w = fmaxf(v.w + b.w, 0.f);
    ((uint2*)g_msg16)[i] = make_uint2(pack2h(v.x, v.y), pack2h(v.z, v.w));
}

// ---------------- h0 = segment max; fp32 + fp16, both dirs ----------------
__global__ void k_h0(const float* __restrict__ h_atom) {
    int g = blockIdx.x;
    int c = threadIdx.x * 4;
    int s0 = g_start[g], s1 = g_start[g + 1];
    float4 m = make_float4(-3.4e38f, -3.4e38f, -3.4e38f, -3.4e38f);
    for (int r = s0; r < s1; r++) {
        float4 v = *(const float4*)&h_atom[(size_t)r * Hdim + c];
        m.x = fmaxf(m.x, v.x); m.y = fmaxf(m.y, v.y);
        m.z = fmaxf(m.z, v.z); m.w = fmaxf(m.w, v.w);
    }
    if (s1 == s0) m = make_float4(0.f, 0.f, 0.f, 0.f);
    int fi = g * Hdim + c;
    uint2 p = make_uint2(pack2h(m.x, m.y), pack2h(m.z, m.w));
#pragma unroll
    for (int d = 0; d < 2; d++) {
        *(float4*)&g_h[d][0][fi] = m;
        ((uint2*)g_h16[d][0])[fi / 4] = p;
    }
}

// =====================================================================
// Input GEMM (fp16): XG[n x 3072] = msg @ W_ih^T + b_ih
// Block 128m x 128n, K-chunk 16, 8 warps (2m x 4n), warp 64x32.
// =====================================================================
__global__ void __launch_bounds__(256) k_gemm_f16(
    const float* __restrict__ bi_f, const float* __restrict__ bi_b, int n)
{
    __shared__ uint32_t sA[2048], sB[2048];
    int dir = blockIdx.z;
    const uint32_t* W = g_w16[dir * 2];
    const float* Bv = dir ? bi_b : bi_f;
    float* XG = g_xg[dir];
    int n0 = blockIdx.x * 128;
    int m0 = blockIdx.y * 128;
    int tid = threadIdx.x, lane = tid & 31, wid = tid >> 5;
    int wm = wid >> 2, wn = wid & 3;

    int ar = tid >> 1, ao = tid & 1;
    int br = tid >> 1, bo = tid & 1;

    float acc[4][4][4];
#pragma unroll
    for (int m = 0; m < 4; m++)
#pragma unroll
        for (int q = 0; q < 4; q++)
#pragma unroll
            for (int e = 0; e < 4; e++) acc[m][q][e] = 0.f;

    uint4 pA, pB;

    auto ld = [&](int k0) {
        int rg = m0 + ar;
        if (rg < n) pA = *(const uint4*)&g_msg16[rg * (Hdim / 2) + (k0 + ao * 8) / 2];
        else        pA = make_uint4(0, 0, 0, 0);
        pB = *(const uint4*)&W[(size_t)(n0 + br) * (Hdim / 2) + (k0 + bo * 8) / 2];
    };
    auto st = [&](int buf) {
        int mfr = ar >> 4, rh = (ar >> 3) & 1, reg = ao * 2 + rh;
        int base = buf * 1024 + (mfr * 32 + (ar & 7) * 4) * 4 + reg;
        const uint32_t* p = (const uint32_t*)&pA;
#pragma unroll
        for (int i = 0; i < 4; i++) sA[base + i * 4] = p[i];
        int nfr = br >> 3, nl = br & 7;
        int base2 = buf * 1024 + (nfr * 32 + nl * 4) * 2 + bo;
        const uint32_t* q = (const uint32_t*)&pB;
#pragma unroll
        for (int i = 0; i < 4; i++) sB[base2 + i * 2] = q[i];
    };
    auto comp = [&](int buf) {
        uint4 a[4]; uint2 b[4];
#pragma unroll
        for (int m = 0; m < 4; m++)
            a[m] = *(const uint4*)&sA[buf * 1024 + ((wm * 4 + m) * 32 + lane) * 4];
#pragma unroll
        for (int q = 0; q < 4; q++)
            b[q] = *(const uint2*)&sB[buf * 1024 + ((wn * 4 + q) * 32 + lane) * 2];
#pragma unroll
        for (int m = 0; m < 4; m++)
#pragma unroll
            for (int q = 0; q < 4; q++)
                mma16f(acc[m][q], (const uint32_t*)&a[m], (const uint32_t*)&b[q]);
    };

    ld(0); st(0); __syncthreads();
    for (int c = 0; c < Hdim / 16; c++) {
        int buf = c & 1;
        if (c + 1 < Hdim / 16) ld((c + 1) * 16);
        comp(buf);
        if (c + 1 < Hdim / 16) { st(buf ^ 1); __syncthreads(); }
    }

#pragma unroll
    for (int m = 0; m < 4; m++)
#pragma unroll
        for (int half = 0; half < 2; half++) {
            int row = m0 + wm * 64 + m * 16 + (lane >> 2) + half * 8;
            if (row < n) {
#pragma unroll
                for (int q = 0; q < 4; q++) {
                    int col = n0 + wn * 32 + q * 8 + (lane & 3) * 2;
                    float2 o;
                    o.x = acc[m][q][half * 2 + 0] + Bv[col];
                    o.y = acc[m][q][half * 2 + 1] + Bv[col + 1];
                    *(float2*)&XG[(size_t)row * H3 + col] = o;
                }
            }
        }
}

// =====================================================================
// GRU step (fp16): gates = h @ W_hh^T + fused epilogue.
// Block 64g x 96n (32 j x 3 gates), K-chunk 32, 32 iters,
// 3 smem buffers + 2-deep register prefetch. 8 warps (2m x 4n).
// grid (32 jtiles, 4 gtiles, 2 dirs) = 256 CTAs -> 2/SM.
// =====================================================================
#define NCH 32   // 1024 / 32

__global__ void __launch_bounds__(256, 2) k_step_f16(
    const float* __restrict__ bhh_f, const float* __restrict__ bih_f,
    const float* __restrict__ bhh_b, const float* __restrict__ bih_b,
    float* __restrict__ out, int s)
{
    __shared__ uint32_t sA[3 * 1024], sB[3 * 1536];
    int dir = blockIdx.z;
    const uint32_t* W = g_w16[dir * 2 + 1];
    const float* Bh = dir ? bhh_b : bhh_f;
    const float* Bi = dir ? bih_b : bih_f;
    const float* xg = g_xg[dir];
    int par = s & 1;
    const float*    hin  = g_h[dir][par];
    float*          hout = g_h[dir][par ^ 1];
    const uint32_t* h16  = g_h16[dir][par];
    uint32_t*       ho16 = g_h16[dir][par ^ 1];
    int tstep = dir ? (Ldim - 1 - s) : s;

    int j0 = blockIdx.x * 32;
    int g0 = blockIdx.y * 64;
    int tid = threadIdx.x, lane = tid & 31, wid = tid >> 5;
    int wm = wid >> 2, wn = wid & 3;

    // A loader: all 256 threads, one uint4 (octet) each: row ar, k-octet aoct
    int ar = tid >> 2, aoct = tid & 3;
    // B loader: tid < 192, two uint4 each: row br, k16-half bk (octets 2bk, 2bk+1)
    bool hasB = tid < 192;
    int br = tid >> 1, bk = tid & 1;
    int wrowB = (br >> 5) * Hdim + j0 + (br & 31);

    float acc[2][3][4];
#pragma unroll
    for (int m = 0; m < 2; m++)
#pragma unroll
        for (int gt = 0; gt < 3; gt++)
#pragma unroll
            for (int e = 0; e < 4; e++) acc[m][gt][e] = 0.f;

    uint4 rA[2], rB0[2], rB1[2];

    auto ld = [&](int c, int rs) {
        rA[rs] = *(const uint4*)&h16[(g0 + ar) * (Hdim / 2) + c * 16 + aoct * 4];
        if (hasB) {
            const uint32_t* wp = &W[(size_t)wrowB * (Hdim / 2) + c * 16 + bk * 8];
            rB0[rs] = *(const uint4*)wp;
            rB1[rs] = *(const uint4*)(wp + 4);
        }
    };
    auto st = [&](int buf, int rs) {
        {
            int kf = aoct >> 1, oo = aoct & 1;
            int mfr = ar >> 4, rr = ar & 15;
            int reg = oo * 2 + (rr >> 3);
            int base = buf * 1024 + ((kf * 4 + mfr) * 32 + (rr & 7) * 4) * 4 + reg;
            const uint32_t* p = (const uint32_t*)&rA[rs];
#pragma unroll
            for (int e = 0; e < 4; e++) sA[base + e * 4] = p[e];
        }
        if (hasB) {
            int nfr = br >> 3, nl = br & 7;
            int base = buf * 1536 + ((bk * 12 + nfr) * 32 + nl * 4) * 2;
            const uint32_t* p0 = (const uint32_t*)&rB0[rs];
            const uint32_t* p1 = (const uint32_t*)&rB1[rs];
#pragma unroll
            for (int e = 0; e < 4; e++) {
                sB[base + e * 2 + 0] = p0[e];
                sB[base + e * 2 + 1] = p1[e];
            }
        }
    };
    auto comp = [&](int buf) {
#pragma unroll
        for (int kf = 0; kf < 2; kf++) {
            uint4 a[2]; uint2 b[3];
#pragma unroll
            for (int m = 0; m < 2; m++)
                a[m] = *(const uint4*)&sA[buf * 1024 + ((kf * 4 + wm * 2 + m) * 32 + lane) * 4];
#pragma unroll
            for (int gt = 0; gt < 3; gt++)
                b[gt] = *(const uint2*)&sB[buf * 1536 + ((kf * 12 + gt * 4 + wn) * 32 + lane) * 2];
#pragma unroll
            for (int m = 0; m < 2; m++)
#pragma unroll
                for (int gt = 0; gt < 3; gt++)
                    mma16f(acc[m][gt], (const uint32_t*)&a[m], (const uint32_t*)&b[gt]);
        }
    };

    // prologue: chunk0 -> buf0, chunk1 in regs
    ld(0, 0); st(0, 0); ld(1, 1);
    __syncthreads();
#pragma unroll 6
    for (int c = 0; c < NCH; c++) {
        int buf = c % 3;
        if (c + 2 < NCH) ld(c + 2, c & 1);
        comp(buf);
        if (c + 1 < NCH) {
            st((c + 1) % 3, (c + 1) & 1);
            __syncthreads();
        }
    }

    // ---- fused gate epilogue + fp16 round + scatter ----
#pragma unroll
    for (int m = 0; m < 2; m++) {
#pragma unroll
        for (int half = 0; half < 2; half++) {
            int g = g0 + (wm * 2 + m) * 16 + (lane >> 2) + half * 8;
            int stt = g_start[g];
            int cnt = g_start[g + 1] - stt;
            bool valid = (tstep < cnt);
            size_t abase = (size_t)(stt + tstep) * H3;
            int j = j0 + wn * 8 + (lane & 3) * 2;
            float hv[2];
#pragma unroll
            for (int cp = 0; cp < 2; cp++) {
                int jj = j + cp;
                float xr, xz, xn;
                if (valid) {
                    xr = xg[abase + jj];
                    xz = xg[abase + Hdim + jj];
                    xn = xg[abase + 2 * Hdim + jj];
                } else {
                    xr = Bi[jj]; xz = Bi[Hdim + jj]; xn = Bi[2 * Hdim + jj];
                }
                int e = half * 2 + cp;
                float r  = 1.f / (1.f + expf(-(xr + acc[m][0][e] + Bh[jj])));
                float z  = 1.f / (1.f + expf(-(xz + acc[m][1][e] + Bh[Hdim + jj])));
                float nn = tanhf(xn + r * (acc[m][2][e] + Bh[2 * Hdim + jj]));
                float hp = hin[g * Hdim + jj];
                hv[cp] = (1.f - z) * nn + z * hp;
                hout[g * Hdim + jj] = hv[cp];
                if (valid)
                    out[(size_t)(stt + tstep) * (2 * Hdim) + (size_t)dir * Hdim + jj] = hv[cp];
            }
            ho16[(g * Hdim + j) / 2] = pack2h(hv[0], hv[1]);
        }
    }
}

// ---------------- host launcher ----------------
extern "C" void kernel_launch(void* const* d_in, const int* in_sizes, int n_in,
                              void* d_out, int out_size)
{
    int nAtoms = in_sizes[0] / Hdim;

    const float* h_atom = (const float*)d_in[0];
    int iBatch, iBias, iWihF, iWhhF, iBihF, iBhhF, iWihB, iWhhB, iBihB, iBhhB;
    if (in_sizes[1] == nAtoms) {
        iBatch = 1; iBias = 2; iWihF = 3; iWhhF = 4; iBihF = 5; iBhhF = 6;
        iWihB = 7; iWhhB = 8; iBihB = 9; iBhhB = 10;
    } else {
        iBias = 1; iWihF = 2; iWhhF = 3; iBihF = 4; iBhhF = 5;
        iWihB = 6; iWhhB = 7; iBihB = 8; iBhhB = 9; iBatch = 10;
    }

    const int*   batch = (const int*)d_in[iBatch];
    const float* bias  = (const float*)d_in[iBias];
    const float* wihf  = (const float*)d_in[iWihF];
    const float* whhf  = (const float*)d_in[iWhhF];
    const float* bihf  = (const float*)d_in[iBihF];
    const float* bhhf  = (const float*)d_in[iBhhF];
    const float* wihb  = (const float*)d_in[iWihB];
    const float* whhb  = (const float*)d_in[iWhhB];
    const float* bihb  = (const float*)d_in[iBihB];
    const float* bhhb  = (const float*)d_in[iBhhB];
    float* out = (float*)d_out;

    k_meta<<<1, 512>>>(batch, nAtoms);

    dim3 gw(WELEM / 4 / 256, 4);
    k_round_w<<<gw, 256>>>(wihf, whhf, wihb, whhb);

    int n4 = nAtoms * Hdim / 4;
    k_message<<<(n4 + 255) / 256, 256>>>(h_atom, bias, n4);

    k_h0<<<Gdim, 256>>>(h_atom);

    dim3 gg(H3 / 128, (nAtoms + 127) / 128, 2);
    k_gemm_f16<<<gg, 256>>>(bihf, bihb, nAtoms);

    dim3 gs(Hdim / 32, Gdim / 64, 2);
    for (int s = 0; s < Ldim; s++) {
        k_step_f16<<<gs, 256>>>(bhhf, bihf, bhhb, bihb, out, s);
    }
}